// round 2
// baseline (speedup 1.0000x reference)
#include <cuda_runtime.h>
#include <cuda_bf16.h>

// Problem constants
#define BATCH 1024
#define HID   512
#define TSZ   24
#define PLEN  256

// Layer-kernel tiling
#define BM 64       // batch rows per CTA
#define BN 32       // gate columns per CTA (each has 3 weight parts r/z/n)
#define BK 8        // k-slice
#define APAD 4

// Ping-pong state buffers (device globals: no allocation allowed)
__device__ float g_h0[2][BATCH * HID];
__device__ float g_h1[2][BATCH * HID];
__device__ float g_val[2][BATCH * TSZ];

// ---------------------------------------------------------------------------
// helpers
// ---------------------------------------------------------------------------
union F2U { float2 f; unsigned long long u; };

__device__ __forceinline__ void ffma2(float2& d, const float2 a, const float2 b) {
    F2U D, A, B;
    D.f = d; A.f = a; B.f = b;
    asm("fma.rn.f32x2 %0, %1, %2, %0;" : "+l"(D.u) : "l"(A.u), "l"(B.u));
    d = D.f;
}

__device__ __forceinline__ float sigf(float x) {
    return 1.0f / (1.0f + __expf(-x));
}
__device__ __forceinline__ float tanhf_fast(float x) {
    return 1.0f - 2.0f / (__expf(2.0f * x) + 1.0f);
}

// ---------------------------------------------------------------------------
// Fused GRU layer: h' = GRUCell(x, h)
// Per CTA: 64 rows x 32 gate-cols. 256 threads: tm=tid>>5 (row octet),
// tn=tid&31 (one col). Per thread: 8 rows x 1 col x {r,z,ni,nh} accumulators.
// Warp = one row octet x 32 contiguous cols -> coalesced everything.
// Grid: (BATCH/BM, HID/BN) = (16,16) = 256 CTAs.
// ---------------------------------------------------------------------------
template<int KX>
__global__ __launch_bounds__(256, 2)
void gru_layer_kernel(const float* __restrict__ x,
                      const float* __restrict__ hin,
                      float* __restrict__ hout,
                      const float* __restrict__ Wih,
                      const float* __restrict__ Whh,
                      const float* __restrict__ bih,
                      const float* __restrict__ bhh)
{
    __shared__ __align__(16) float  As[BK][BM + APAD];
    __shared__ __align__(16) float2 Ws[BK][3][BN];   // weights pre-duplicated (w,w)

    const int tid = threadIdx.x;
    const int tm  = tid >> 5;          // 0..7: rows tm*8 .. tm*8+7
    const int tn  = tid & 31;          // 0..31: one column
    const int rowBase = blockIdx.x * BM;
    const int colBase = blockIdx.y * BN;
    const int j = colBase + tn;

    // accumulators: pair p covers rows tm*8+2p, tm*8+2p+1
    float2 aR[4], aZ[4], aN[4], aH[4];
    {
        const float br = bih[j]           + bhh[j];
        const float bz = bih[HID + j]     + bhh[HID + j];
        const float bi = bih[2 * HID + j];
        const float bh = bhh[2 * HID + j];
        #pragma unroll
        for (int p = 0; p < 4; p++) {
            aR[p] = make_float2(br, br);
            aZ[p] = make_float2(bz, bz);
            aN[p] = make_float2(bi, bi);
            aH[p] = make_float2(bh, bh);
        }
    }

    // loader mapping
    const bool al = tid < 128;
    const int  lb = tid >> 1;            // 0..63 (row)  [valid when al]
    const int  lk = (tid & 1) << 2;      // 0 or 4
    const bool wl = tid < 192;
    const int  wg = tid / 64;            // gate 0..2    [valid when wl]
    const int  wj = (tid & 63) >> 1;     // 0..31 (local col)
    const int  wk = (tid & 1) << 2;      // 0 or 4

    #pragma unroll
    for (int ph = 0; ph < 2; ph++) {
        const float* __restrict__ A = ph ? hin : x;
        const float* __restrict__ W = ph ? Whh : Wih;
        const int K = ph ? HID : KX;
        float2 (*aNt) = ph ? aH : aN;   // n-part target

        const float* Arow = A + (size_t)(rowBase + lb) * K + lk;
        const float* Wrow = wl ? (W + (size_t)(wg * HID + colBase + wj) * K + wk) : W;

        float4 av = al ? *(const float4*)(Arow) : make_float4(0.f, 0.f, 0.f, 0.f);
        float4 wv = wl ? *(const float4*)(Wrow) : make_float4(0.f, 0.f, 0.f, 0.f);

        for (int k0 = 0; k0 < K; k0 += BK) {
            // stage current tile
            if (al) {
                #pragma unroll
                for (int i = 0; i < 4; i++)
                    As[lk + i][lb] = ((const float*)&av)[i];
            }
            if (wl) {
                #pragma unroll
                for (int i = 0; i < 4; i++) {
                    const float w = ((const float*)&wv)[i];
                    Ws[wk + i][wg][wj] = make_float2(w, w);
                }
            }
            __syncthreads();

            // prefetch next tile into registers
            const bool more = (k0 + BK) < K;
            if (more) {
                if (al) av = *(const float4*)(Arow + k0 + BK);
                if (wl) wv = *(const float4*)(Wrow + k0 + BK);
            }

            // compute
            #pragma unroll
            for (int kk = 0; kk < BK; kk++) {
                const float4 a0 = *(const float4*)&As[kk][tm * 8];
                const float4 a1 = *(const float4*)&As[kk][tm * 8 + 4];
                const float2 ap[4] = {
                    make_float2(a0.x, a0.y), make_float2(a0.z, a0.w),
                    make_float2(a1.x, a1.y), make_float2(a1.z, a1.w)
                };
                const float2 wr = Ws[kk][0][tn];
                const float2 wz = Ws[kk][1][tn];
                const float2 wn = Ws[kk][2][tn];
                #pragma unroll
                for (int p = 0; p < 4; p++) {
                    ffma2(aR[p],  ap[p], wr);
                    ffma2(aZ[p],  ap[p], wz);
                    ffma2(aNt[p], ap[p], wn);
                }
            }
            __syncthreads();
        }
    }

    // GRU epilogue: r=sig, z=sig, n=tanh(in + r*hn), h' = (1-z)*n + z*h
    #pragma unroll
    for (int p = 0; p < 4; p++) {
        const int r0 = rowBase + tm * 8 + 2 * p;
        const float h0c = hin[(size_t)r0 * HID + j];
        const float h1c = hin[(size_t)(r0 + 1) * HID + j];
        const float rr0 = sigf(aR[p].x);
        const float rr1 = sigf(aR[p].y);
        const float zz0 = sigf(aZ[p].x);
        const float zz1 = sigf(aZ[p].y);
        const float nn0 = tanhf_fast(aN[p].x + rr0 * aH[p].x);
        const float nn1 = tanhf_fast(aN[p].y + rr1 * aH[p].y);
        hout[(size_t)r0 * HID + j]       = (1.0f - zz0) * nn0 + zz0 * h0c;
        hout[(size_t)(r0 + 1) * HID + j] = (1.0f - zz1) * nn1 + zz1 * h1c;
    }
}

// ---------------------------------------------------------------------------
// Output head: out = sigmoid(relu(h1) @ Wout^T + bout)  (B x 24)
// Warp-per-row: lane holds 16 h1 values, 24 dot products, butterfly reduce.
// Wout staged in smem (48KB). Grid BATCH/8 = 128, block 256 (8 warps).
// ---------------------------------------------------------------------------
__global__ __launch_bounds__(256)
void out_kernel(const float* __restrict__ h1,
                const float* __restrict__ Wout,
                const float* __restrict__ bout,
                float* __restrict__ outputs,
                float* __restrict__ val_out,
                int step)
{
    __shared__ __align__(16) float Wsh[TSZ * HID];   // 48KB, same layout as Wout

    const int tid = threadIdx.x;
    // stage Wout
    #pragma unroll
    for (int i = 0; i < (TSZ * HID / 4) / 256; i++)
        ((float4*)Wsh)[tid + i * 256] = ((const float4*)Wout)[tid + i * 256];
    __syncthreads();

    const int wid  = tid >> 5;
    const int lane = tid & 31;
    const int row  = blockIdx.x * 8 + wid;

    // load this row's activations: 16 floats per lane, relu applied
    float xv[16];
    {
        const float4* hrow = (const float4*)(h1 + (size_t)row * HID);
        #pragma unroll
        for (int q = 0; q < 4; q++) {
            float4 v = hrow[lane * 4 + q];
            xv[q * 4 + 0] = fmaxf(v.x, 0.f);
            xv[q * 4 + 1] = fmaxf(v.y, 0.f);
            xv[q * 4 + 2] = fmaxf(v.z, 0.f);
            xv[q * 4 + 3] = fmaxf(v.w, 0.f);
        }
    }

    float s[TSZ];
    #pragma unroll
    for (int jj = 0; jj < TSZ; jj++) {
        const float4* wr = (const float4*)&Wsh[jj * HID + lane * 16];
        float acc = 0.f;
        #pragma unroll
        for (int q = 0; q < 4; q++) {
            const float4 w = wr[q];
            acc = fmaf(xv[q * 4 + 0], w.x, acc);
            acc = fmaf(xv[q * 4 + 1], w.y, acc);
            acc = fmaf(xv[q * 4 + 2], w.z, acc);
            acc = fmaf(xv[q * 4 + 3], w.w, acc);
        }
        s[jj] = acc;
    }

    // butterfly reduce all 24 sums across the warp
    #pragma unroll
    for (int off = 16; off >= 1; off >>= 1) {
        #pragma unroll
        for (int jj = 0; jj < TSZ; jj++)
            s[jj] += __shfl_xor_sync(0xFFFFFFFFu, s[jj], off);
    }

    if (lane < TSZ) {
        const float v = sigf(s[lane] + bout[lane]);
        outputs[(size_t)row * (PLEN * TSZ) + (size_t)step * TSZ + lane] = v;
        val_out[row * TSZ + lane] = v;
    }
}

// ---------------------------------------------------------------------------
// init / final copy
// ---------------------------------------------------------------------------
__global__ void init_kernel(const float* __restrict__ hidden,
                            float* __restrict__ h0,
                            float* __restrict__ h1,
                            float* __restrict__ val)
{
    const int i = blockIdx.x * blockDim.x + threadIdx.x;
    if (i < BATCH * HID) {
        h0[i] = hidden[i];
        h1[i] = hidden[BATCH * HID + i];
    }
    if (i < BATCH * TSZ) val[i] = 0.0f;
}

__global__ void fin_kernel(const float* __restrict__ h0,
                           const float* __restrict__ h1,
                           float* __restrict__ dst)
{
    const int i = blockIdx.x * blockDim.x + threadIdx.x;
    if (i < BATCH * HID) {
        dst[i] = h0[i];
        dst[BATCH * HID + i] = h1[i];
    }
}

// ---------------------------------------------------------------------------
// host: record the full 256-step rollout into the capture stream
// ---------------------------------------------------------------------------
extern "C" void kernel_launch(void* const* d_in, const int* in_sizes, int n_in,
                              void* d_out, int out_size)
{
    const float* hidden = (const float*)d_in[0];
    const float* Wih0   = (const float*)d_in[1];
    const float* Whh0   = (const float*)d_in[2];
    const float* bih0   = (const float*)d_in[3];
    const float* bhh0   = (const float*)d_in[4];
    const float* Wih1   = (const float*)d_in[5];
    const float* Whh1   = (const float*)d_in[6];
    const float* bih1   = (const float*)d_in[7];
    const float* bhh1   = (const float*)d_in[8];
    const float* Wout   = (const float*)d_in[9];
    const float* bout   = (const float*)d_in[10];
    float* out = (float*)d_out;

    float *h0b, *h1b, *vb;
    cudaGetSymbolAddress((void**)&h0b, g_h0);
    cudaGetSymbolAddress((void**)&h1b, g_h1);
    cudaGetSymbolAddress((void**)&vb,  g_val);
    float* h0p[2]  = { h0b, h0b + BATCH * HID };
    float* h1p[2]  = { h1b, h1b + BATCH * HID };
    float* valp[2] = { vb,  vb  + BATCH * TSZ };

    init_kernel<<<(BATCH * HID + 255) / 256, 256>>>(hidden, h0p[0], h1p[0], valp[0]);

    const dim3 lgrid(BATCH / BM, HID / BN);
    for (int s = 0; s < PLEN; s++) {
        const int cur = s & 1;
        const int nxt = cur ^ 1;
        gru_layer_kernel<TSZ><<<lgrid, 256>>>(valp[cur], h0p[cur], h0p[nxt],
                                              Wih0, Whh0, bih0, bhh0);
        gru_layer_kernel<HID><<<lgrid, 256>>>(h0p[nxt], h1p[cur], h1p[nxt],
                                              Wih1, Whh1, bih1, bhh1);
        out_kernel<<<BATCH / 8, 256>>>(h1p[nxt], Wout, bout, out, valp[nxt], s);
    }
    // after 256 steps (even), final hidden sits in buffer index 0
    fin_kernel<<<(BATCH * HID + 255) / 256, 256>>>(h0p[0], h1p[0],
                                                   out + (size_t)BATCH * PLEN * TSZ);
}

// round 3
// speedup vs baseline: 1.2178x; 1.2178x over previous
#include <cuda_runtime.h>
#include <cuda_bf16.h>

// Problem constants
#define BATCH 1024
#define HID   512
#define TSZ   24
#define PLEN  256

// Layer-kernel tiling: CTA = BM rows x BN gate-cols, 128 threads
#define BM 64
#define BN 32
#define BK 8

// Ping-pong state buffers (device globals: no allocation allowed)
__device__ float g_h0[2][BATCH * HID];
__device__ float g_h1[2][BATCH * HID];
__device__ float g_val[2][BATCH * TSZ];

// ---------------------------------------------------------------------------
// helpers
// ---------------------------------------------------------------------------
union F2U { float2 f; unsigned long long u; };

__device__ __forceinline__ void ffma2(float2& d, const float2 a, const float2 b) {
    F2U D, A, B;
    D.f = d; A.f = a; B.f = b;
    asm("fma.rn.f32x2 %0, %1, %2, %0;" : "+l"(D.u) : "l"(A.u), "l"(B.u));
    d = D.f;
}

__device__ __forceinline__ float sigf(float x) {
    return 1.0f / (1.0f + __expf(-x));
}
__device__ __forceinline__ float tanhf_fast(float x) {
    return 1.0f - 2.0f / (__expf(2.0f * x) + 1.0f);
}

// ---------------------------------------------------------------------------
// Fused GRU layer: h' = GRUCell(x, h)
// Thread = 8 rows x 1 col-pair. Activations stored DUPLICATED (a,a) in smem
// (broadcast reads: 1 wavefront), weights stored plain (adjacent-col float2
// reads: 1 wavefront). 24 FFMA2 : 7 LDS-wf per warp per k -> FMA-bound.
// Grid: (BATCH/BM, HID/BN) = (16,16) = 256 CTAs, 128 threads.
// ---------------------------------------------------------------------------
template<int KX>
__global__ __launch_bounds__(128, 2)
void gru_layer_kernel(const float* __restrict__ x,
                      const float* __restrict__ hin,
                      float* __restrict__ hout,
                      const float* __restrict__ Wih,
                      const float* __restrict__ Whh,
                      const float* __restrict__ bih,
                      const float* __restrict__ bhh)
{
    __shared__ __align__(16) float2 As2[BK][BM];      // duplicated (a,a)
    __shared__ __align__(16) float  Ws[BK][3][BN];    // plain weights

    const int tid = threadIdx.x;          // 0..127
    const int rg  = tid >> 4;             // 0..7 : rows rg*8 .. rg*8+7
    const int cp  = tid & 15;             // 0..15: cols 2cp, 2cp+1
    const int rowBase = blockIdx.x * BM;
    const int colBase = blockIdx.y * BN;
    const int j0 = colBase + 2 * cp;

    // accumulators: [row r within octet], float2 = (col j0, col j0+1)
    float2 aR[8], aZ[8], aN[8], aH[8];
    {
        const float2 bi1 = *(const float2*)&bih[j0];
        const float2 bh1 = *(const float2*)&bhh[j0];
        const float2 bi2 = *(const float2*)&bih[HID + j0];
        const float2 bh2 = *(const float2*)&bhh[HID + j0];
        const float2 bi3 = *(const float2*)&bih[2 * HID + j0];
        const float2 bh3 = *(const float2*)&bhh[2 * HID + j0];
        const float2 br = make_float2(bi1.x + bh1.x, bi1.y + bh1.y);
        const float2 bz = make_float2(bi2.x + bh2.x, bi2.y + bh2.y);
        #pragma unroll
        for (int r = 0; r < 8; r++) {
            aR[r] = br; aZ[r] = bz; aN[r] = bi3; aH[r] = bh3;
        }
    }

    // A loader: thread -> (row, k-half)
    const int lrow = tid >> 1;            // 0..63
    const int lkh  = (tid & 1) << 2;      // 0 or 4
    // W loader: 192 float4 loads; thread does idx=tid, and idx=tid+128 if tid<64
    const int wg1 = tid >> 6;                    // 0..1
    const int wc1 = (tid >> 1) & 31;
    const int wk1 = (tid & 1) << 2;
    const int wc2 = ((tid + 128) >> 1) & 31;     // for tid<64 -> gate 2
    const int wk2 = (tid & 1) << 2;

    #pragma unroll
    for (int ph = 0; ph < 2; ph++) {
        const float* __restrict__ A = ph ? hin : x;
        const float* __restrict__ W = ph ? Whh : Wih;
        const int K = ph ? HID : KX;
        float2* aNt = ph ? aH : aN;       // n-part target

        const float* Arow  = A + (size_t)(rowBase + lrow) * K + lkh;
        const float* Wrow1 = W + (size_t)(wg1 * HID + colBase + wc1) * K + wk1;
        const float* Wrow2 = W + (size_t)(2 * HID + colBase + wc2) * K + wk2;

        float4 av = *(const float4*)(Arow);
        float4 wv1 = *(const float4*)(Wrow1);
        float4 wv2 = (tid < 64) ? *(const float4*)(Wrow2)
                                : make_float4(0.f, 0.f, 0.f, 0.f);

        for (int k0 = 0; k0 < K; k0 += BK) {
            // stage current tile
            #pragma unroll
            for (int i = 0; i < 4; i++) {
                const float a = ((const float*)&av)[i];
                As2[lkh + i][lrow] = make_float2(a, a);
            }
            #pragma unroll
            for (int i = 0; i < 4; i++)
                Ws[wk1 + i][wg1][wc1] = ((const float*)&wv1)[i];
            if (tid < 64) {
                #pragma unroll
                for (int i = 0; i < 4; i++)
                    Ws[wk2 + i][2][wc2] = ((const float*)&wv2)[i];
            }
            __syncthreads();

            // prefetch next tile into registers
            if (k0 + BK < K) {
                av  = *(const float4*)(Arow + k0 + BK);
                wv1 = *(const float4*)(Wrow1 + k0 + BK);
                if (tid < 64) wv2 = *(const float4*)(Wrow2 + k0 + BK);
            }

            // compute
            #pragma unroll
            for (int kk = 0; kk < BK; kk++) {
                float2 ap[8];
                const float4* asrc = (const float4*)&As2[kk][rg * 8];
                #pragma unroll
                for (int q = 0; q < 4; q++) {
                    const float4 v = asrc[q];
                    ap[2 * q]     = make_float2(v.x, v.y);
                    ap[2 * q + 1] = make_float2(v.z, v.w);
                }
                const float2 wr = *(const float2*)&Ws[kk][0][2 * cp];
                const float2 wz = *(const float2*)&Ws[kk][1][2 * cp];
                const float2 wn = *(const float2*)&Ws[kk][2][2 * cp];
                #pragma unroll
                for (int r = 0; r < 8; r++) {
                    ffma2(aR[r],  ap[r], wr);
                    ffma2(aZ[r],  ap[r], wz);
                    ffma2(aNt[r], ap[r], wn);
                }
            }
            __syncthreads();
        }
    }

    // GRU epilogue: r=sig, z=sig, n=tanh(in + r*hn), h' = (1-z)*n + z*h
    #pragma unroll
    for (int r = 0; r < 8; r++) {
        const int R = rowBase + rg * 8 + r;
        const float2 hp = *(const float2*)&hin[(size_t)R * HID + j0];
        const float rr0 = sigf(aR[r].x);
        const float rr1 = sigf(aR[r].y);
        const float zz0 = sigf(aZ[r].x);
        const float zz1 = sigf(aZ[r].y);
        const float nn0 = tanhf_fast(aN[r].x + rr0 * aH[r].x);
        const float nn1 = tanhf_fast(aN[r].y + rr1 * aH[r].y);
        float2 o;
        o.x = (1.0f - zz0) * nn0 + zz0 * hp.x;
        o.y = (1.0f - zz1) * nn1 + zz1 * hp.y;
        *(float2*)&hout[(size_t)R * HID + j0] = o;
    }
}

// ---------------------------------------------------------------------------
// Output head: out = sigmoid(relu(h1) @ Wout^T + bout)  (B x 24)
// Warp-per-row, no smem: Wout (48KB) is L1-resident since all warps read it.
// Grid BATCH/8 = 128, block 256 (8 warps).
// ---------------------------------------------------------------------------
__global__ __launch_bounds__(256)
void out_kernel(const float* __restrict__ h1,
                const float* __restrict__ Wout,
                const float* __restrict__ bout,
                float* __restrict__ outputs,
                float* __restrict__ val_out,
                int step)
{
    const int wid  = threadIdx.x >> 5;
    const int lane = threadIdx.x & 31;
    const int row  = blockIdx.x * 8 + wid;

    // this row's activations: 16 floats per lane, relu applied
    float xv[16];
    {
        const float4* hrow = (const float4*)(h1 + (size_t)row * HID);
        #pragma unroll
        for (int q = 0; q < 4; q++) {
            const float4 v = __ldg(&hrow[lane * 4 + q]);
            xv[q * 4 + 0] = fmaxf(v.x, 0.f);
            xv[q * 4 + 1] = fmaxf(v.y, 0.f);
            xv[q * 4 + 2] = fmaxf(v.z, 0.f);
            xv[q * 4 + 3] = fmaxf(v.w, 0.f);
        }
    }

    float s[TSZ];
    #pragma unroll
    for (int jj = 0; jj < TSZ; jj++) {
        const float4* wr = (const float4*)(Wout + (size_t)jj * HID + lane * 16);
        float acc = 0.f;
        #pragma unroll
        for (int q = 0; q < 4; q++) {
            const float4 w = __ldg(&wr[q]);
            acc = fmaf(xv[q * 4 + 0], w.x, acc);
            acc = fmaf(xv[q * 4 + 1], w.y, acc);
            acc = fmaf(xv[q * 4 + 2], w.z, acc);
            acc = fmaf(xv[q * 4 + 3], w.w, acc);
        }
        s[jj] = acc;
    }

    // butterfly reduce all 24 sums across the warp
    #pragma unroll
    for (int off = 16; off >= 1; off >>= 1) {
        #pragma unroll
        for (int jj = 0; jj < TSZ; jj++)
            s[jj] += __shfl_xor_sync(0xFFFFFFFFu, s[jj], off);
    }

    if (lane < TSZ) {
        const float v = sigf(s[lane] + bout[lane]);
        outputs[(size_t)row * (PLEN * TSZ) + (size_t)step * TSZ + lane] = v;
        val_out[row * TSZ + lane] = v;
    }
}

// ---------------------------------------------------------------------------
// init / final copy
// ---------------------------------------------------------------------------
__global__ void init_kernel(const float* __restrict__ hidden,
                            float* __restrict__ h0,
                            float* __restrict__ h1,
                            float* __restrict__ val)
{
    const int i = blockIdx.x * blockDim.x + threadIdx.x;
    if (i < BATCH * HID) {
        h0[i] = hidden[i];
        h1[i] = hidden[BATCH * HID + i];
    }
    if (i < BATCH * TSZ) val[i] = 0.0f;
}

__global__ void fin_kernel(const float* __restrict__ h0,
                           const float* __restrict__ h1,
                           float* __restrict__ dst)
{
    const int i = blockIdx.x * blockDim.x + threadIdx.x;
    if (i < BATCH * HID) {
        dst[i] = h0[i];
        dst[BATCH * HID + i] = h1[i];
    }
}

// ---------------------------------------------------------------------------
// host: record the full 256-step rollout into the capture stream
// ---------------------------------------------------------------------------
extern "C" void kernel_launch(void* const* d_in, const int* in_sizes, int n_in,
                              void* d_out, int out_size)
{
    const float* hidden = (const float*)d_in[0];
    const float* Wih0   = (const float*)d_in[1];
    const float* Whh0   = (const float*)d_in[2];
    const float* bih0   = (const float*)d_in[3];
    const float* bhh0   = (const float*)d_in[4];
    const float* Wih1   = (const float*)d_in[5];
    const float* Whh1   = (const float*)d_in[6];
    const float* bih1   = (const float*)d_in[7];
    const float* bhh1   = (const float*)d_in[8];
    const float* Wout   = (const float*)d_in[9];
    const float* bout   = (const float*)d_in[10];
    float* out = (float*)d_out;

    float *h0b, *h1b, *vb;
    cudaGetSymbolAddress((void**)&h0b, g_h0);
    cudaGetSymbolAddress((void**)&h1b, g_h1);
    cudaGetSymbolAddress((void**)&vb,  g_val);
    float* h0p[2]  = { h0b, h0b + BATCH * HID };
    float* h1p[2]  = { h1b, h1b + BATCH * HID };
    float* valp[2] = { vb,  vb  + BATCH * TSZ };

    init_kernel<<<(BATCH * HID + 255) / 256, 256>>>(hidden, h0p[0], h1p[0], valp[0]);

    const dim3 lgrid(BATCH / BM, HID / BN);
    for (int s = 0; s < PLEN; s++) {
        const int cur = s & 1;
        const int nxt = cur ^ 1;
        gru_layer_kernel<TSZ><<<lgrid, 128>>>(valp[cur], h0p[cur], h0p[nxt],
                                              Wih0, Whh0, bih0, bhh0);
        gru_layer_kernel<HID><<<lgrid, 128>>>(h0p[nxt], h1p[cur], h1p[nxt],
                                              Wih1, Whh1, bih1, bhh1);
        out_kernel<<<BATCH / 8, 256>>>(h1p[nxt], Wout, bout, out, valp[nxt], s);
    }
    // after 256 steps (even), final hidden sits in buffer index 0
    fin_kernel<<<(BATCH * HID + 255) / 256, 256>>>(h0p[0], h1p[0],
                                                   out + (size_t)BATCH * PLEN * TSZ);
}

// round 4
// speedup vs baseline: 1.7291x; 1.4198x over previous
#include <cuda_runtime.h>
#include <cuda_bf16.h>

// Problem constants
#define BATCH 1024
#define HID   512
#define TSZ   24
#define PLEN  256
#define XPAD  32            // padded input width for layer0 (24 -> 32)

// Layer-kernel tiling: CTA = 64 rows x 64 gate-cols, 256 threads, grid (16,8)
#define BM 64
#define BN 64
#define BKT 16              // k per smem tile
#define APLANE 68           // padded A plane (floats per kk)
#define WPLANE 196          // padded W plane (floats per kk: 3*64 + 4)

// Ping-pong state buffers (device globals: no allocation allowed)
__device__ float g_h0[2][BATCH * HID];
__device__ float g_h1[2][BATCH * HID];
__device__ float g_val[2][BATCH * XPAD];
__device__ float g_Wih0p[3 * HID * XPAD];   // zero-padded Wih0

// ---------------------------------------------------------------------------
// helpers
// ---------------------------------------------------------------------------
union F2U { float2 f; unsigned long long u; };

__device__ __forceinline__ void ffma2(float2& d, const float2 a, const float2 b) {
    F2U D, A, B;
    D.f = d; A.f = a; B.f = b;
    asm("fma.rn.f32x2 %0, %1, %2, %0;" : "+l"(D.u) : "l"(A.u), "l"(B.u));
    d = D.f;
}

__device__ __forceinline__ float sigf(float x) {
    return 1.0f / (1.0f + __expf(-x));
}
__device__ __forceinline__ float tanhf_fast(float x) {
    return 1.0f - 2.0f / (__expf(2.0f * x) + 1.0f);
}

// ---------------------------------------------------------------------------
// Fused GRU layer: h' = GRUCell(x, h)
// Thread = 8 rows x 1 col-pair; lane = (rg<<2)|cpL -> warp = 64 rows x 8 cols.
// Warps cover disjoint col-octets => no redundant weight smem reads.
// Double-buffered smem, 1 barrier per 16-k tile.
// Grid: (BATCH/64, HID/64) = (16,8) = 128 CTAs, 256 threads.
// ---------------------------------------------------------------------------
template<int KX>
__global__ __launch_bounds__(256, 1)
void gru_layer_kernel(const float* __restrict__ x,
                      const float* __restrict__ hin,
                      float* __restrict__ hout,
                      const float* __restrict__ Wih,
                      const float* __restrict__ Whh,
                      const float* __restrict__ bih,
                      const float* __restrict__ bhh)
{
    __shared__ __align__(16) float As[2][BKT * APLANE];
    __shared__ __align__(16) float Ws[2][BKT * WPLANE];

    const int tid  = threadIdx.x;
    const int wid  = tid >> 5;
    const int lane = tid & 31;
    const int rg   = lane >> 2;        // 0..7 : rows rg*8..rg*8+7
    const int cpL  = lane & 3;         // 0..3 : col-pair within warp octet
    const int rowBase = blockIdx.x * BM;
    const int colBase = blockIdx.y * BN;
    const int jloc = wid * 8 + cpL * 2;       // 0..62 (even), local col
    const int j0   = colBase + jloc;

    // accumulators (col-pair): r, z, n-input, n-hidden
    float2 aR[8], aZ[8], aN[8], aH[8];
    {
        const float2 bi1 = *(const float2*)&bih[j0];
        const float2 bh1 = *(const float2*)&bhh[j0];
        const float2 bi2 = *(const float2*)&bih[HID + j0];
        const float2 bh2 = *(const float2*)&bhh[HID + j0];
        const float2 bi3 = *(const float2*)&bih[2 * HID + j0];
        const float2 bh3 = *(const float2*)&bhh[2 * HID + j0];
        const float2 br = make_float2(bi1.x + bh1.x, bi1.y + bh1.y);
        const float2 bz = make_float2(bi2.x + bh2.x, bi2.y + bh2.y);
        #pragma unroll
        for (int r = 0; r < 8; r++) {
            aR[r] = br; aZ[r] = bz; aN[r] = bi3; aH[r] = bh3;
        }
    }

    // loader mapping: c/arow = tid>>2 (0..63), koff = (tid&3)*4
    const int lrc  = tid >> 2;
    const int koff = (tid & 3) << 2;

    int buf = 0;

    #pragma unroll
    for (int ph = 0; ph < 2; ph++) {
        const float* __restrict__ A = ph ? hin : x;
        const float* __restrict__ W = ph ? Whh : Wih;
        const int K = ph ? HID : KX;
        float2* aNt = ph ? aH : aN;

        const float* Aptr = A + (size_t)(rowBase + lrc) * K + koff;
        const float* Wp0 = W + (size_t)(colBase + lrc) * K + koff;
        const float* Wp1 = W + (size_t)(HID + colBase + lrc) * K + koff;
        const float* Wp2 = W + (size_t)(2 * HID + colBase + lrc) * K + koff;

        // prologue: load + stage tile 0
        float4 av = *(const float4*)(Aptr);
        float4 w0 = *(const float4*)(Wp0);
        float4 w1 = *(const float4*)(Wp1);
        float4 w2 = *(const float4*)(Wp2);
        {
            float* Ac = As[buf];
            float* Wc = Ws[buf];
            #pragma unroll
            for (int i = 0; i < 4; i++) {
                Ac[(koff + i) * APLANE + lrc] = ((const float*)&av)[i];
                Wc[(koff + i) * WPLANE + lrc]           = ((const float*)&w0)[i];
                Wc[(koff + i) * WPLANE + 64 + lrc]      = ((const float*)&w1)[i];
                Wc[(koff + i) * WPLANE + 128 + lrc]     = ((const float*)&w2)[i];
            }
        }
        __syncthreads();

        const int nT = K / BKT;
        for (int t = 0; t < nT; t++) {
            const bool more = (t + 1) < nT;
            if (more) {
                const int off = (t + 1) * BKT;
                av = *(const float4*)(Aptr + off);
                w0 = *(const float4*)(Wp0 + off);
                w1 = *(const float4*)(Wp1 + off);
                w2 = *(const float4*)(Wp2 + off);
            }

            // compute on buf
            {
                const float* Ac = As[buf];
                const float* Wc = Ws[buf];
                #pragma unroll
                for (int kk = 0; kk < BKT; kk++) {
                    float a[8];
                    *(float4*)&a[0] = *(const float4*)&Ac[kk * APLANE + rg * 8];
                    *(float4*)&a[4] = *(const float4*)&Ac[kk * APLANE + rg * 8 + 4];
                    const float2 wr = *(const float2*)&Wc[kk * WPLANE + jloc];
                    const float2 wz = *(const float2*)&Wc[kk * WPLANE + 64 + jloc];
                    const float2 wn = *(const float2*)&Wc[kk * WPLANE + 128 + jloc];
                    #pragma unroll
                    for (int r = 0; r < 8; r++) {
                        const float2 ap = make_float2(a[r], a[r]);
                        ffma2(aR[r],  ap, wr);
                        ffma2(aZ[r],  ap, wz);
                        ffma2(aNt[r], ap, wn);
                    }
                }
            }

            if (more) {
                float* An = As[buf ^ 1];
                float* Wn = Ws[buf ^ 1];
                #pragma unroll
                for (int i = 0; i < 4; i++) {
                    An[(koff + i) * APLANE + lrc] = ((const float*)&av)[i];
                    Wn[(koff + i) * WPLANE + lrc]       = ((const float*)&w0)[i];
                    Wn[(koff + i) * WPLANE + 64 + lrc]  = ((const float*)&w1)[i];
                    Wn[(koff + i) * WPLANE + 128 + lrc] = ((const float*)&w2)[i];
                }
            }
            __syncthreads();
            buf ^= 1;
        }
    }

    // GRU epilogue: r=sig, z=sig, n=tanh(in + r*hn), h' = (1-z)*n + z*h
    #pragma unroll
    for (int r = 0; r < 8; r++) {
        const int R = rowBase + rg * 8 + r;
        const float2 hp = *(const float2*)&hin[(size_t)R * HID + j0];
        const float rr0 = sigf(aR[r].x);
        const float rr1 = sigf(aR[r].y);
        const float zz0 = sigf(aZ[r].x);
        const float zz1 = sigf(aZ[r].y);
        const float nn0 = tanhf_fast(aN[r].x + rr0 * aH[r].x);
        const float nn1 = tanhf_fast(aN[r].y + rr1 * aH[r].y);
        float2 o;
        o.x = (1.0f - zz0) * nn0 + zz0 * hp.x;
        o.y = (1.0f - zz1) * nn1 + zz1 * hp.y;
        *(float2*)&hout[(size_t)R * HID + j0] = o;
    }
}

// ---------------------------------------------------------------------------
// Output head: out = sigmoid(relu(h1) @ Wout^T + bout)  (B x 24)
// 2 warps per row (split-K 256 each) + smem combine. Grid 256, block 256.
// ---------------------------------------------------------------------------
__global__ __launch_bounds__(256)
void out_kernel(const float* __restrict__ h1,
                const float* __restrict__ Wout,
                const float* __restrict__ bout,
                float* __restrict__ outputs,
                float* __restrict__ val_out,
                int step)
{
    __shared__ float red[8][TSZ + 1];

    const int tid  = threadIdx.x;
    const int wid  = tid >> 5;
    const int lane = tid & 31;
    const int row  = blockIdx.x * 4 + (wid >> 1);
    const int half = wid & 1;
    const int base = half * 256;

    // this warp's K-half of the row, relu applied: 8 floats/lane
    float xv[8];
    {
        const float4* hrow = (const float4*)(h1 + (size_t)row * HID + base);
        #pragma unroll
        for (int q = 0; q < 2; q++) {
            const float4 v = __ldg(&hrow[lane * 2 + q]);
            xv[q * 4 + 0] = fmaxf(v.x, 0.f);
            xv[q * 4 + 1] = fmaxf(v.y, 0.f);
            xv[q * 4 + 2] = fmaxf(v.z, 0.f);
            xv[q * 4 + 3] = fmaxf(v.w, 0.f);
        }
    }

    float s[TSZ];
    #pragma unroll
    for (int jj = 0; jj < TSZ; jj++) {
        const float4* wr = (const float4*)(Wout + (size_t)jj * HID + base);
        float acc = 0.f;
        #pragma unroll
        for (int q = 0; q < 2; q++) {
            const float4 w = __ldg(&wr[lane * 2 + q]);
            acc = fmaf(xv[q * 4 + 0], w.x, acc);
            acc = fmaf(xv[q * 4 + 1], w.y, acc);
            acc = fmaf(xv[q * 4 + 2], w.z, acc);
            acc = fmaf(xv[q * 4 + 3], w.w, acc);
        }
        s[jj] = acc;
    }

    #pragma unroll
    for (int off = 16; off >= 1; off >>= 1) {
        #pragma unroll
        for (int jj = 0; jj < TSZ; jj++)
            s[jj] += __shfl_xor_sync(0xFFFFFFFFu, s[jj], off);
    }

    if (lane < TSZ) red[wid][lane] = s[lane];
    __syncthreads();

    if (half == 0 && lane < TSZ) {
        const float v = sigf(red[wid][lane] + red[wid + 1][lane] + bout[lane]);
        outputs[(size_t)row * (PLEN * TSZ) + (size_t)step * TSZ + lane] = v;
        val_out[row * XPAD + lane] = v;
    }
}

// ---------------------------------------------------------------------------
// init (state copy + val zero + padded-weight build) / final copy
// ---------------------------------------------------------------------------
__global__ void init_kernel(const float* __restrict__ hidden,
                            const float* __restrict__ Wih0,
                            float* __restrict__ h0,
                            float* __restrict__ h1,
                            float* __restrict__ valAll,   // both ping-pong buffers
                            float* __restrict__ Wih0p)
{
    const int i = blockIdx.x * blockDim.x + threadIdx.x;
    if (i < BATCH * HID) {
        h0[i] = hidden[i];
        h1[i] = hidden[BATCH * HID + i];
    }
    if (i < 2 * BATCH * XPAD) valAll[i] = 0.0f;
    if (i < 3 * HID * XPAD) {
        const int r = i / XPAD;
        const int k = i % XPAD;
        Wih0p[i] = (k < TSZ) ? Wih0[r * TSZ + k] : 0.0f;
    }
}

__global__ void fin_kernel(const float* __restrict__ h0,
                           const float* __restrict__ h1,
                           float* __restrict__ dst)
{
    const int i = blockIdx.x * blockDim.x + threadIdx.x;
    if (i < BATCH * HID) {
        dst[i] = h0[i];
        dst[BATCH * HID + i] = h1[i];
    }
}

// ---------------------------------------------------------------------------
// host: record the full 256-step rollout into the capture stream
// ---------------------------------------------------------------------------
extern "C" void kernel_launch(void* const* d_in, const int* in_sizes, int n_in,
                              void* d_out, int out_size)
{
    const float* hidden = (const float*)d_in[0];
    const float* Wih0   = (const float*)d_in[1];
    const float* Whh0   = (const float*)d_in[2];
    const float* bih0   = (const float*)d_in[3];
    const float* bhh0   = (const float*)d_in[4];
    const float* Wih1   = (const float*)d_in[5];
    const float* Whh1   = (const float*)d_in[6];
    const float* bih1   = (const float*)d_in[7];
    const float* bhh1   = (const float*)d_in[8];
    const float* Wout   = (const float*)d_in[9];
    const float* bout   = (const float*)d_in[10];
    float* out = (float*)d_out;

    float *h0b, *h1b, *vb, *wpad;
    cudaGetSymbolAddress((void**)&h0b,  g_h0);
    cudaGetSymbolAddress((void**)&h1b,  g_h1);
    cudaGetSymbolAddress((void**)&vb,   g_val);
    cudaGetSymbolAddress((void**)&wpad, g_Wih0p);
    float* h0p[2]  = { h0b, h0b + BATCH * HID };
    float* h1p[2]  = { h1b, h1b + BATCH * HID };
    float* valp[2] = { vb,  vb  + BATCH * XPAD };

    init_kernel<<<(BATCH * HID + 255) / 256, 256>>>(hidden, Wih0, h0p[0], h1p[0],
                                                    vb, wpad);

    const dim3 lgrid(BATCH / BM, HID / BN);
    for (int s = 0; s < PLEN; s++) {
        const int cur = s & 1;
        const int nxt = cur ^ 1;
        gru_layer_kernel<XPAD><<<lgrid, 256>>>(valp[cur], h0p[cur], h0p[nxt],
                                               wpad, Whh0, bih0, bhh0);
        gru_layer_kernel<HID><<<lgrid, 256>>>(h0p[nxt], h1p[cur], h1p[nxt],
                                              Wih1, Whh1, bih1, bhh1);
        out_kernel<<<BATCH / 4, 256>>>(h1p[nxt], Wout, bout, out, valp[nxt], s);
    }
    // after 256 steps (even), final hidden sits in buffer index 0
    fin_kernel<<<(BATCH * HID + 255) / 256, 256>>>(h0p[0], h1p[0],
                                                   out + (size_t)BATCH * PLEN * TSZ);
}

// round 7
// speedup vs baseline: 1.9268x; 1.1144x over previous
#include <cuda_runtime.h>
#include <cuda_bf16.h>
#include <cstdint>

// Problem constants
#define BATCH 1024
#define HID   512
#define TSZ   24
#define PLEN  256
#define XP0   32          // padded layer0 input width (24 -> 32)

// Layer tile config: CTA = 128 rows x 32 gate-cols, 8 warps
#define TM 128
#define TN 32
#define KT 16             // k per tile
#define AST 24            // smem row stride (bf16 elems) for A and W tiles

// ---------------------------------------------------------------------------
// Device state (no allocation allowed -> __device__ globals)
// ---------------------------------------------------------------------------
__device__ float         g_h0f[2][BATCH * HID];
__device__ float         g_h1f[2][BATCH * HID];
__device__ __nv_bfloat16 g_h0h[2][BATCH * HID], g_h0l[2][BATCH * HID];
__device__ __nv_bfloat16 g_h1h[2][BATCH * HID], g_h1l[2][BATCH * HID];
__device__ __nv_bfloat16 g_valh[2][BATCH * XP0], g_vall[2][BATCH * XP0];
__device__ __nv_bfloat16 g_w0xh[3 * HID * XP0], g_w0xl[3 * HID * XP0];
__device__ __nv_bfloat16 g_w0hh[3 * HID * HID], g_w0hl[3 * HID * HID];
__device__ __nv_bfloat16 g_w1xh[3 * HID * HID], g_w1xl[3 * HID * HID];
__device__ __nv_bfloat16 g_w1hh[3 * HID * HID], g_w1hl[3 * HID * HID];

// ---------------------------------------------------------------------------
// helpers
// ---------------------------------------------------------------------------
__device__ __forceinline__ float sigf(float x) { return 1.0f / (1.0f + __expf(-x)); }
__device__ __forceinline__ float tanhf_fast(float x) {
    return 1.0f - 2.0f / (__expf(2.0f * x) + 1.0f);
}

__device__ __forceinline__ uint32_t smem_u32(const void* p) {
    uint32_t a;
    asm("{ .reg .u64 t; cvta.to.shared.u64 t, %1; cvt.u32.u64 %0, t; }" : "=r"(a) : "l"(p));
    return a;
}

__device__ __forceinline__ void cpa16(uint32_t dst, const void* src) {
    asm volatile("cp.async.cg.shared.global [%0], [%1], 16;" :: "r"(dst), "l"(src) : "memory");
}
__device__ __forceinline__ void cpa_commit() {
    asm volatile("cp.async.commit_group;" ::: "memory");
}
template<int N>
__device__ __forceinline__ void cpa_wait() {
    asm volatile("cp.async.wait_group %0;" :: "n"(N) : "memory");
}

__device__ __forceinline__ void ldsm4(uint32_t* r, uint32_t addr) {
    asm volatile("ldmatrix.sync.aligned.m8n8.x4.shared.b16 {%0,%1,%2,%3}, [%4];"
                 : "=r"(r[0]), "=r"(r[1]), "=r"(r[2]), "=r"(r[3]) : "r"(addr));
}

__device__ __forceinline__ void mma_bf16(float* c, const uint32_t* a,
                                         uint32_t b0, uint32_t b1) {
    asm volatile(
        "mma.sync.aligned.m16n8k16.row.col.f32.bf16.bf16.f32 "
        "{%0,%1,%2,%3}, {%4,%5,%6,%7}, {%8,%9}, {%0,%1,%2,%3};"
        : "+f"(c[0]), "+f"(c[1]), "+f"(c[2]), "+f"(c[3])
        : "r"(a[0]), "r"(a[1]), "r"(a[2]), "r"(a[3]), "r"(b0), "r"(b1));
}

__device__ __forceinline__ void split_bf16(float x, __nv_bfloat16& h, __nv_bfloat16& l) {
    h = __float2bfloat16(x);
    l = __float2bfloat16(x - __bfloat162float(h));
}

// ---------------------------------------------------------------------------
// GRU layer via mma.sync bf16-split (fp32 accum).
// LAYER=0: x=val[cur] (K=32),  h=h0[cur] -> h0[nxt]
// LAYER=1: x=h0[nxt]  (K=512), h=h1[cur] -> h1[nxt]
// Warp = 16 rows; planes r,z always accumulate; plane slot 2 of W (n-gate)
// goes to inn-frags in x-phase, hn-frags in h-phase.
// Grid (8,16) = 128 CTAs, 256 threads.
// ---------------------------------------------------------------------------
template<int LAYER>
__global__ __launch_bounds__(256, 1)
void gru_mma_kernel(int cur, const float* __restrict__ bih, const float* __restrict__ bhh)
{
    constexpr int KX  = (LAYER == 0) ? XP0 : HID;
    constexpr int NXT = KX / KT;
    constexpr int NT  = NXT + HID / KT;
    const int nxt = cur ^ 1;

    const __nv_bfloat16* __restrict__ xh = (LAYER == 0) ? g_valh[cur] : g_h0h[nxt];
    const __nv_bfloat16* __restrict__ xl = (LAYER == 0) ? g_vall[cur] : g_h0l[nxt];
    const __nv_bfloat16* __restrict__ hh = (LAYER == 0) ? g_h0h[cur] : g_h1h[cur];
    const __nv_bfloat16* __restrict__ hl = (LAYER == 0) ? g_h0l[cur] : g_h1l[cur];
    const float* __restrict__ hinf       = (LAYER == 0) ? g_h0f[cur] : g_h1f[cur];
    float* __restrict__ houtf            = (LAYER == 0) ? g_h0f[nxt] : g_h1f[nxt];
    __nv_bfloat16* __restrict__ houth    = (LAYER == 0) ? g_h0h[nxt] : g_h1h[nxt];
    __nv_bfloat16* __restrict__ houtl    = (LAYER == 0) ? g_h0l[nxt] : g_h1l[nxt];
    const __nv_bfloat16* __restrict__ Wxh  = (LAYER == 0) ? g_w0xh : g_w1xh;
    const __nv_bfloat16* __restrict__ Wxl  = (LAYER == 0) ? g_w0xl : g_w1xl;
    const __nv_bfloat16* __restrict__ Whhh = (LAYER == 0) ? g_w0hh : g_w1hh;
    const __nv_bfloat16* __restrict__ Whhl = (LAYER == 0) ? g_w0hl : g_w1hl;

    // smem: [stage][hi/lo] A: 128x16 @stride 24; W: 96x16 @stride 24
    __shared__ __align__(16) __nv_bfloat16 sA[2][2][TM * AST];
    __shared__ __align__(16) __nv_bfloat16 sW[2][2][3 * TN * AST];

    const int tid  = threadIdx.x;
    const int w    = tid >> 5;
    const int l    = tid & 31;
    const int rowBase = blockIdx.x * TM;
    const int colBase = blockIdx.y * TN;

    // accumulators: [plane r,z,inn,hn][nf][reg]
    float cA[4][4][4];
    {
        const int c4 = l & 3;
        #pragma unroll
        for (int nf = 0; nf < 4; nf++) {
            const int j0 = colBase + nf * 8 + 2 * c4;
            const float br0 = __ldg(bih + j0)     + __ldg(bhh + j0);
            const float br1 = __ldg(bih + j0 + 1) + __ldg(bhh + j0 + 1);
            const float bz0 = __ldg(bih + HID + j0)     + __ldg(bhh + HID + j0);
            const float bz1 = __ldg(bih + HID + j0 + 1) + __ldg(bhh + HID + j0 + 1);
            const float bi0 = __ldg(bih + 2 * HID + j0);
            const float bi1 = __ldg(bih + 2 * HID + j0 + 1);
            const float bn0 = __ldg(bhh + 2 * HID + j0);
            const float bn1 = __ldg(bhh + 2 * HID + j0 + 1);
            cA[0][nf][0] = br0; cA[0][nf][1] = br1; cA[0][nf][2] = br0; cA[0][nf][3] = br1;
            cA[1][nf][0] = bz0; cA[1][nf][1] = bz1; cA[1][nf][2] = bz0; cA[1][nf][3] = bz1;
            cA[2][nf][0] = bi0; cA[2][nf][1] = bi1; cA[2][nf][2] = bi0; cA[2][nf][3] = bi1;
            cA[3][nf][0] = bn0; cA[3][nf][1] = bn1; cA[3][nf][2] = bn0; cA[3][nf][3] = bn1;
        }
    }

    // lane offsets for ldmatrix (bf16-element offsets within tiles)
    const int aOff = (w * 16 + (l & 7) + (((l >> 3) & 1) << 3)) * AST + ((l >> 4) << 3);
    const int wOff = ((l & 7) + (((l >> 4) & 1) << 3)) * AST + (((l >> 3) & 1) << 3);

    // stage loader mapping
    const int ar = tid >> 1;            // A row 0..127
    const int ac = (tid & 1) << 3;      // k-half offset (elems)

    // ---- staging lambda (issues cp.async for tile t into stage buf) ----
    auto stage = [&](int t) {
        const int buf = t & 1;
        const bool xph = (t < NXT);
        const __nv_bfloat16* Ah = xph ? xh : hh;
        const __nv_bfloat16* Al = xph ? xl : hl;
        const __nv_bfloat16* Wh = xph ? Wxh : Whhh;
        const __nv_bfloat16* Wl = xph ? Wxl : Whhl;
        const int K    = xph ? KX : HID;
        const int koff = (xph ? t : t - NXT) * KT;

        // A: 128 rows x 16, hi and lo (one 16B chunk per thread each)
        {
            const size_t g = (size_t)(rowBase + ar) * K + koff + ac;
            cpa16(smem_u32(&sA[buf][0][ar * AST + ac]), Ah + g);
            cpa16(smem_u32(&sA[buf][1][ar * AST + ac]), Al + g);
        }
        // W: 96 rows x 16, hi+lo = 384 16B chunks over 256 threads
        #pragma unroll
        for (int i = tid; i < 384; i += 256) {
            const int part = i / 192;
            const int idx  = i % 192;
            const int rr   = idx >> 1;
            const int cc   = (idx & 1) << 3;
            const int grow = (rr >> 5) * HID + colBase + (rr & 31);
            const __nv_bfloat16* src = (part ? Wl : Wh) + (size_t)grow * K + koff + cc;
            cpa16(smem_u32(&sW[buf][part][rr * AST + cc]), src);
        }
    };

    // ---- compute lambda for tile t ----
    auto compute = [&](int t) {
        const int buf = t & 1;
        const bool xph = (t < NXT);
        uint32_t ah[4], al[4];
        ldsm4(ah, smem_u32(&sA[buf][0][0]) + aOff * 2);
        ldsm4(al, smem_u32(&sA[buf][1][0]) + aOff * 2);

        const uint32_t wbh = smem_u32(&sW[buf][0][0]) + wOff * 2;
        const uint32_t wbl = smem_u32(&sW[buf][1][0]) + wOff * 2;

        #pragma unroll
        for (int p = 0; p < 3; p++) {
            uint32_t bh[8], bl[8];
            ldsm4(bh,     wbh + (p * 32) * AST * 2);
            ldsm4(bh + 4, wbh + (p * 32 + 16) * AST * 2);
            ldsm4(bl,     wbl + (p * 32) * AST * 2);
            ldsm4(bl + 4, wbl + (p * 32 + 16) * AST * 2);
            float (*C)[4] = (p == 2) ? (xph ? cA[2] : cA[3]) : cA[p];
            #pragma unroll
            for (int nf = 0; nf < 4; nf++) {
                mma_bf16(C[nf], ah, bh[2 * nf], bh[2 * nf + 1]);
                mma_bf16(C[nf], al, bh[2 * nf], bh[2 * nf + 1]);
                mma_bf16(C[nf], ah, bl[2 * nf], bl[2 * nf + 1]);
            }
        }
    };

    // ---- pipelined main loop ----
    stage(0);
    cpa_commit();
    for (int t = 0; t < NT; t++) {
        if (t + 1 < NT) {
            stage(t + 1);
            cpa_commit();
            cpa_wait<1>();
        } else {
            cpa_wait<0>();
        }
        __syncthreads();
        compute(t);
        __syncthreads();
    }

    // ---- GRU epilogue ----
    const int g  = l >> 2;
    const int c4 = l & 3;
    const int R0 = rowBase + w * 16 + g;
    const int R1 = R0 + 8;
    #pragma unroll
    for (int nf = 0; nf < 4; nf++) {
        const int j0 = colBase + nf * 8 + 2 * c4;
        const float2 h0v = *(const float2*)&hinf[(size_t)R0 * HID + j0];
        const float2 h1v = *(const float2*)&hinf[(size_t)R1 * HID + j0];
        float o[4];
        const float hvv[4] = { h0v.x, h0v.y, h1v.x, h1v.y };
        #pragma unroll
        for (int i = 0; i < 4; i++) {
            const float r_ = sigf(cA[0][nf][i]);
            const float z_ = sigf(cA[1][nf][i]);
            const float n_ = tanhf_fast(cA[2][nf][i] + r_ * cA[3][nf][i]);
            o[i] = (1.0f - z_) * n_ + z_ * hvv[i];
        }
        *(float2*)&houtf[(size_t)R0 * HID + j0] = make_float2(o[0], o[1]);
        *(float2*)&houtf[(size_t)R1 * HID + j0] = make_float2(o[2], o[3]);
        __nv_bfloat16 h0a, l0a, h0b, l0b, h1a, l1a, h1b, l1b;
        split_bf16(o[0], h0a, l0a); split_bf16(o[1], h0b, l0b);
        split_bf16(o[2], h1a, l1a); split_bf16(o[3], h1b, l1b);
        *(__nv_bfloat162*)&houth[(size_t)R0 * HID + j0] = __halves2bfloat162(h0a, h0b);
        *(__nv_bfloat162*)&houtl[(size_t)R0 * HID + j0] = __halves2bfloat162(l0a, l0b);
        *(__nv_bfloat162*)&houth[(size_t)R1 * HID + j0] = __halves2bfloat162(h1a, h1b);
        *(__nv_bfloat162*)&houtl[(size_t)R1 * HID + j0] = __halves2bfloat162(l1a, l1b);
    }
}

// ---------------------------------------------------------------------------
// Output head: out = sigmoid(relu(h1) @ Wout^T + bout)  (B x 24)
// Warp per row: stage relu(h1-row) to smem, lane j<24 owns one output col.
// Grid 128, block 256 (8 warps).
// ---------------------------------------------------------------------------
__global__ __launch_bounds__(256)
void out_kernel(int cur,
                const float* __restrict__ Wout,
                const float* __restrict__ bout,
                float* __restrict__ outputs,
                int step)
{
    __shared__ __align__(16) float hs[8][HID];
    const int nxt = cur ^ 1;
    const float* __restrict__ h1 = g_h1f[nxt];

    const int w    = threadIdx.x >> 5;
    const int lane = threadIdx.x & 31;
    const int row  = blockIdx.x * 8 + w;

    // stage relu(h1 row) into this warp's smem slice
    {
        const float4* hr = (const float4*)(h1 + (size_t)row * HID);
        #pragma unroll
        for (int q = 0; q < 4; q++) {
            float4 v = __ldg(&hr[lane + q * 32]);
            v.x = fmaxf(v.x, 0.f); v.y = fmaxf(v.y, 0.f);
            v.z = fmaxf(v.z, 0.f); v.w = fmaxf(v.w, 0.f);
            ((float4*)hs[w])[lane + q * 32] = v;
        }
    }
    __syncwarp();

    if (lane < TSZ) {
        const float4* wr = (const float4*)(Wout + (size_t)lane * HID);
        float a0 = 0.f, a1 = 0.f, a2 = 0.f, a3 = 0.f;
        #pragma unroll 8
        for (int kb = 0; kb < HID / 4; kb++) {
            const float4 hv = ((const float4*)hs[w])[kb];
            const float4 wv = __ldg(&wr[kb]);
            a0 = fmaf(hv.x, wv.x, a0);
            a1 = fmaf(hv.y, wv.y, a1);
            a2 = fmaf(hv.z, wv.z, a2);
            a3 = fmaf(hv.w, wv.w, a3);
        }
        const float v = sigf((a0 + a1) + (a2 + a3) + __ldg(bout + lane));
        outputs[(size_t)row * (PLEN * TSZ) + (size_t)step * TSZ + lane] = v;
        __nv_bfloat16 vh, vl;
        split_bf16(v, vh, vl);
        g_valh[nxt][row * XP0 + lane] = vh;
        g_vall[nxt][row * XP0 + lane] = vl;
    }
}

// ---------------------------------------------------------------------------
// init: copy/split initial hidden, zero val buffers, split + pad weights
// ---------------------------------------------------------------------------
__global__ void init_kernel(const float* __restrict__ hidden,
                            const float* __restrict__ Wih0,
                            const float* __restrict__ Whh0,
                            const float* __restrict__ Wih1,
                            const float* __restrict__ Whh1)
{
    const int i = blockIdx.x * blockDim.x + threadIdx.x;
    const __nv_bfloat16 z16 = __float2bfloat16(0.0f);

    if (i < BATCH * HID) {
        const float a = hidden[i];
        const float b = hidden[BATCH * HID + i];
        g_h0f[0][i] = a;
        g_h1f[0][i] = b;
        split_bf16(a, g_h0h[0][i], g_h0l[0][i]);
        split_bf16(b, g_h1h[0][i], g_h1l[0][i]);
    }
    if (i < 2 * BATCH * XP0) {
        (&g_valh[0][0])[i] = z16;
        (&g_vall[0][0])[i] = z16;
    }
    if (i < 3 * HID * XP0) {
        const int r = i / XP0;
        const int k = i % XP0;
        const float ww = (k < TSZ) ? Wih0[r * TSZ + k] : 0.0f;
        split_bf16(ww, g_w0xh[i], g_w0xl[i]);
    }
    if (i < 3 * HID * HID) {
        split_bf16(Whh0[i], g_w0hh[i], g_w0hl[i]);
        split_bf16(Wih1[i], g_w1xh[i], g_w1xl[i]);
        split_bf16(Whh1[i], g_w1hh[i], g_w1hl[i]);
    }
}

__global__ void fin_kernel(float* __restrict__ dst)
{
    const int i = blockIdx.x * blockDim.x + threadIdx.x;
    if (i < BATCH * HID) {
        dst[i] = g_h0f[0][i];
        dst[BATCH * HID + i] = g_h1f[0][i];
    }
}

// ---------------------------------------------------------------------------
// host
// ---------------------------------------------------------------------------
extern "C" void kernel_launch(void* const* d_in, const int* in_sizes, int n_in,
                              void* d_out, int out_size)
{
    const float* hidden = (const float*)d_in[0];
    const float* Wih0   = (const float*)d_in[1];
    const float* Whh0   = (const float*)d_in[2];
    const float* bih0   = (const float*)d_in[3];
    const float* bhh0   = (const float*)d_in[4];
    const float* Wih1   = (const float*)d_in[5];
    const float* Whh1   = (const float*)d_in[6];
    const float* bih1   = (const float*)d_in[7];
    const float* bhh1   = (const float*)d_in[8];
    const float* Wout   = (const float*)d_in[9];
    const float* bout   = (const float*)d_in[10];
    float* out = (float*)d_out;

    init_kernel<<<(3 * HID * HID + 255) / 256, 256>>>(hidden, Wih0, Whh0, Wih1, Whh1);

    const dim3 lgrid(BATCH / TM, HID / TN);   // (8, 16)
    for (int s = 0; s < PLEN; s++) {
        const int cur = s & 1;
        gru_mma_kernel<0><<<lgrid, 256>>>(cur, bih0, bhh0);
        gru_mma_kernel<1><<<lgrid, 256>>>(cur, bih1, bhh1);
        out_kernel<<<BATCH / 8, 256>>>(cur, Wout, bout, out, s);
    }
    fin_kernel<<<(BATCH * HID + 255) / 256, 256>>>(out + (size_t)BATCH * PLEN * TSZ);
}

// round 8
// speedup vs baseline: 2.1787x; 1.1307x over previous
#include <cuda_runtime.h>
#include <cuda_bf16.h>
#include <cstdint>

// Problem constants
#define BATCH 1024
#define HID   512
#define TSZ   24
#define PLEN  256
#define XP0   32          // padded layer0 input width (24 -> 32)

// GRU layer tile config: CTA = 128 rows x 32 gate-cols, 8 warps
#define TM 128
#define TN 32
#define KT 16             // k per tile
#define AST 24            // smem row stride (bf16 elems)

// dynamic smem layout for gru kernel (bytes)
#define G_APART 6144              // one A part: 128*24*2
#define G_WPART 4608              // one W part: 96*24*2
#define G_STAGE (2*G_APART + 2*G_WPART)   // 21504
#define G_SMEM  (4*G_STAGE)               // 86016

// ---------------------------------------------------------------------------
// Device state (no allocation allowed -> __device__ globals)
// ---------------------------------------------------------------------------
__device__ float         g_h0f[2][BATCH * HID];
__device__ float         g_h1f[2][BATCH * HID];
__device__ __nv_bfloat16 g_h0h[2][BATCH * HID], g_h0l[2][BATCH * HID];
__device__ __nv_bfloat16 g_h1h[2][BATCH * HID], g_h1l[2][BATCH * HID];
__device__ __nv_bfloat16 g_h1rh[2][BATCH * HID], g_h1rl[2][BATCH * HID]; // relu(h1) split
__device__ __nv_bfloat16 g_valh[2][BATCH * XP0], g_vall[2][BATCH * XP0];
__device__ __nv_bfloat16 g_w0xh[3 * HID * XP0], g_w0xl[3 * HID * XP0];
__device__ __nv_bfloat16 g_w0hh[3 * HID * HID], g_w0hl[3 * HID * HID];
__device__ __nv_bfloat16 g_w1xh[3 * HID * HID], g_w1xl[3 * HID * HID];
__device__ __nv_bfloat16 g_w1hh[3 * HID * HID], g_w1hl[3 * HID * HID];
__device__ __nv_bfloat16 g_wouth[32 * HID], g_woutl[32 * HID];  // padded Wout

// ---------------------------------------------------------------------------
// helpers
// ---------------------------------------------------------------------------
__device__ __forceinline__ float sigf(float x) { return 1.0f / (1.0f + __expf(-x)); }
__device__ __forceinline__ float tanhf_fast(float x) {
    return 1.0f - 2.0f / (__expf(2.0f * x) + 1.0f);
}

__device__ __forceinline__ uint32_t smem_u32(const void* p) {
    uint32_t a;
    asm("{ .reg .u64 t; cvta.to.shared.u64 t, %1; cvt.u32.u64 %0, t; }" : "=r"(a) : "l"(p));
    return a;
}

__device__ __forceinline__ void cpa16(uint32_t dst, const void* src) {
    asm volatile("cp.async.cg.shared.global [%0], [%1], 16;" :: "r"(dst), "l"(src) : "memory");
}
__device__ __forceinline__ void cpa_commit() {
    asm volatile("cp.async.commit_group;" ::: "memory");
}
template<int N>
__device__ __forceinline__ void cpa_wait() {
    asm volatile("cp.async.wait_group %0;" :: "n"(N) : "memory");
}

__device__ __forceinline__ void ldsm4(uint32_t* r, uint32_t addr) {
    asm volatile("ldmatrix.sync.aligned.m8n8.x4.shared.b16 {%0,%1,%2,%3}, [%4];"
                 : "=r"(r[0]), "=r"(r[1]), "=r"(r[2]), "=r"(r[3]) : "r"(addr));
}

__device__ __forceinline__ void mma_bf16(float* c, const uint32_t* a,
                                         uint32_t b0, uint32_t b1) {
    asm volatile(
        "mma.sync.aligned.m16n8k16.row.col.f32.bf16.bf16.f32 "
        "{%0,%1,%2,%3}, {%4,%5,%6,%7}, {%8,%9}, {%0,%1,%2,%3};"
        : "+f"(c[0]), "+f"(c[1]), "+f"(c[2]), "+f"(c[3])
        : "r"(a[0]), "r"(a[1]), "r"(a[2]), "r"(a[3]), "r"(b0), "r"(b1));
}

__device__ __forceinline__ void split_bf16(float x, __nv_bfloat16& h, __nv_bfloat16& l) {
    h = __float2bfloat16(x);
    l = __float2bfloat16(x - __bfloat162float(h));
}

// ---------------------------------------------------------------------------
// GRU layer via mma.sync bf16-split, 4-stage cp.async pipeline, 1 sync/tile.
// LAYER=0: x=val[cur] (K=32),  h=h0[cur] -> h0[nxt]
// LAYER=1: x=h0[nxt]  (K=512), h=h1[cur] -> h1[nxt] (+ relu split buffers)
// Grid (8,16) = 128 CTAs, 256 threads.
// ---------------------------------------------------------------------------
template<int LAYER>
__global__ __launch_bounds__(256, 1)
void gru_mma_kernel(int cur, const float* __restrict__ bih, const float* __restrict__ bhh)
{
    constexpr int KX  = (LAYER == 0) ? XP0 : HID;
    constexpr int NXT = KX / KT;
    constexpr int NT  = NXT + HID / KT;
    const int nxt = cur ^ 1;

    const __nv_bfloat16* __restrict__ xh = (LAYER == 0) ? g_valh[cur] : g_h0h[nxt];
    const __nv_bfloat16* __restrict__ xl = (LAYER == 0) ? g_vall[cur] : g_h0l[nxt];
    const __nv_bfloat16* __restrict__ hh = (LAYER == 0) ? g_h0h[cur] : g_h1h[cur];
    const __nv_bfloat16* __restrict__ hl = (LAYER == 0) ? g_h0l[cur] : g_h1l[cur];
    const float* __restrict__ hinf       = (LAYER == 0) ? g_h0f[cur] : g_h1f[cur];
    float* __restrict__ houtf            = (LAYER == 0) ? g_h0f[nxt] : g_h1f[nxt];
    __nv_bfloat16* __restrict__ houth    = (LAYER == 0) ? g_h0h[nxt] : g_h1h[nxt];
    __nv_bfloat16* __restrict__ houtl    = (LAYER == 0) ? g_h0l[nxt] : g_h1l[nxt];
    const __nv_bfloat16* __restrict__ Wxh  = (LAYER == 0) ? g_w0xh : g_w1xh;
    const __nv_bfloat16* __restrict__ Wxl  = (LAYER == 0) ? g_w0xl : g_w1xl;
    const __nv_bfloat16* __restrict__ Whhh = (LAYER == 0) ? g_w0hh : g_w1hh;
    const __nv_bfloat16* __restrict__ Whhl = (LAYER == 0) ? g_w0hl : g_w1hl;

    extern __shared__ __align__(16) char sm[];
    auto sAp = [&](int s, int part) -> char* { return sm + s * G_STAGE + part * G_APART; };
    auto sWp = [&](int s, int part) -> char* {
        return sm + s * G_STAGE + 2 * G_APART + part * G_WPART;
    };

    const int tid  = threadIdx.x;
    const int w    = tid >> 5;
    const int l    = tid & 31;
    const int rowBase = blockIdx.x * TM;
    const int colBase = blockIdx.y * TN;

    // accumulators: [plane r,z,inn,hn][nf][reg]
    float cA[4][4][4];
    {
        const int c4 = l & 3;
        #pragma unroll
        for (int nf = 0; nf < 4; nf++) {
            const int j0 = colBase + nf * 8 + 2 * c4;
            const float br0 = __ldg(bih + j0)     + __ldg(bhh + j0);
            const float br1 = __ldg(bih + j0 + 1) + __ldg(bhh + j0 + 1);
            const float bz0 = __ldg(bih + HID + j0)     + __ldg(bhh + HID + j0);
            const float bz1 = __ldg(bih + HID + j0 + 1) + __ldg(bhh + HID + j0 + 1);
            const float bi0 = __ldg(bih + 2 * HID + j0);
            const float bi1 = __ldg(bih + 2 * HID + j0 + 1);
            const float bn0 = __ldg(bhh + 2 * HID + j0);
            const float bn1 = __ldg(bhh + 2 * HID + j0 + 1);
            cA[0][nf][0] = br0; cA[0][nf][1] = br1; cA[0][nf][2] = br0; cA[0][nf][3] = br1;
            cA[1][nf][0] = bz0; cA[1][nf][1] = bz1; cA[1][nf][2] = bz0; cA[1][nf][3] = bz1;
            cA[2][nf][0] = bi0; cA[2][nf][1] = bi1; cA[2][nf][2] = bi0; cA[2][nf][3] = bi1;
            cA[3][nf][0] = bn0; cA[3][nf][1] = bn1; cA[3][nf][2] = bn0; cA[3][nf][3] = bn1;
        }
    }

    // lane offsets for ldmatrix (bf16-element offsets within tiles)
    const int aOff = (w * 16 + (l & 7) + (((l >> 3) & 1) << 3)) * AST + ((l >> 4) << 3);
    const int wOff = ((l & 7) + (((l >> 4) & 1) << 3)) * AST + (((l >> 3) & 1) << 3);

    // stage loader mapping
    const int ar = tid >> 1;            // A row 0..127
    const int ac = (tid & 1) << 3;      // k-half offset (elems)

    auto stage = [&](int t) {
        const int buf = t & 3;
        const bool xph = (t < NXT);
        const __nv_bfloat16* Ah = xph ? xh : hh;
        const __nv_bfloat16* Al = xph ? xl : hl;
        const __nv_bfloat16* Wh = xph ? Wxh : Whhh;
        const __nv_bfloat16* Wl = xph ? Wxl : Whhl;
        const int K    = xph ? KX : HID;
        const int koff = (xph ? t : t - NXT) * KT;

        {
            const size_t g = (size_t)(rowBase + ar) * K + koff + ac;
            cpa16(smem_u32(sAp(buf, 0) + (ar * AST + ac) * 2), Ah + g);
            cpa16(smem_u32(sAp(buf, 1) + (ar * AST + ac) * 2), Al + g);
        }
        #pragma unroll
        for (int i = tid; i < 384; i += 256) {
            const int part = i / 192;
            const int idx  = i % 192;
            const int rr   = idx >> 1;
            const int cc   = (idx & 1) << 3;
            const int grow = (rr >> 5) * HID + colBase + (rr & 31);
            const __nv_bfloat16* src = (part ? Wl : Wh) + (size_t)grow * K + koff + cc;
            cpa16(smem_u32(sWp(buf, part) + (rr * AST + cc) * 2), src);
        }
    };

    auto compute = [&](int t) {
        const int buf = t & 3;
        const bool xph = (t < NXT);
        uint32_t ah[4], al[4];
        ldsm4(ah, smem_u32(sAp(buf, 0)) + aOff * 2);
        ldsm4(al, smem_u32(sAp(buf, 1)) + aOff * 2);

        const uint32_t wbh = smem_u32(sWp(buf, 0)) + wOff * 2;
        const uint32_t wbl = smem_u32(sWp(buf, 1)) + wOff * 2;

        #pragma unroll
        for (int p = 0; p < 3; p++) {
            uint32_t bh[8], bl[8];
            ldsm4(bh,     wbh + (p * 32) * AST * 2);
            ldsm4(bh + 4, wbh + (p * 32 + 16) * AST * 2);
            ldsm4(bl,     wbl + (p * 32) * AST * 2);
            ldsm4(bl + 4, wbl + (p * 32 + 16) * AST * 2);
            float (*C)[4] = (p == 2) ? (xph ? cA[2] : cA[3]) : cA[p];
            #pragma unroll
            for (int nf = 0; nf < 4; nf++) {
                mma_bf16(C[nf], ah, bh[2 * nf], bh[2 * nf + 1]);
                mma_bf16(C[nf], al, bh[2 * nf], bh[2 * nf + 1]);
                mma_bf16(C[nf], ah, bl[2 * nf], bl[2 * nf + 1]);
            }
        }
    };

    // ---- 4-stage pipeline, one barrier per tile ----
    stage(0); cpa_commit();
    stage(1); cpa_commit();
    stage(2); cpa_commit();
    for (int t = 0; t < NT; t++) {
        cpa_wait<2>();          // tile t landed (all but 2 newest groups done)
        __syncthreads();        // all warps finished compute(t-1); smem visible
        compute(t);
        if (t + 3 < NT) stage(t + 3);   // writes buf (t-1)%4: WAR-safe after sync
        cpa_commit();           // empty group in tail keeps wait<2> semantics
    }

    // ---- GRU epilogue ----
    const int g  = l >> 2;
    const int c4 = l & 3;
    const int R0 = rowBase + w * 16 + g;
    const int R1 = R0 + 8;
    #pragma unroll
    for (int nf = 0; nf < 4; nf++) {
        const int j0 = colBase + nf * 8 + 2 * c4;
        const float2 h0v = *(const float2*)&hinf[(size_t)R0 * HID + j0];
        const float2 h1v = *(const float2*)&hinf[(size_t)R1 * HID + j0];
        float o[4];
        const float hvv[4] = { h0v.x, h0v.y, h1v.x, h1v.y };
        #pragma unroll
        for (int i = 0; i < 4; i++) {
            const float r_ = sigf(cA[0][nf][i]);
            const float z_ = sigf(cA[1][nf][i]);
            const float n_ = tanhf_fast(cA[2][nf][i] + r_ * cA[3][nf][i]);
            o[i] = (1.0f - z_) * n_ + z_ * hvv[i];
        }
        *(float2*)&houtf[(size_t)R0 * HID + j0] = make_float2(o[0], o[1]);
        *(float2*)&houtf[(size_t)R1 * HID + j0] = make_float2(o[2], o[3]);
        __nv_bfloat16 h0a, l0a, h0b, l0b, h1a, l1a, h1b, l1b;
        split_bf16(o[0], h0a, l0a); split_bf16(o[1], h0b, l0b);
        split_bf16(o[2], h1a, l1a); split_bf16(o[3], h1b, l1b);
        *(__nv_bfloat162*)&houth[(size_t)R0 * HID + j0] = __halves2bfloat162(h0a, h0b);
        *(__nv_bfloat162*)&houtl[(size_t)R0 * HID + j0] = __halves2bfloat162(l0a, l0b);
        *(__nv_bfloat162*)&houth[(size_t)R1 * HID + j0] = __halves2bfloat162(h1a, h1b);
        *(__nv_bfloat162*)&houtl[(size_t)R1 * HID + j0] = __halves2bfloat162(l1a, l1b);

        if (LAYER == 1) {
            // relu split for the output head
            __nv_bfloat16 rh0a, rl0a, rh0b, rl0b, rh1a, rl1a, rh1b, rl1b;
            split_bf16(fmaxf(o[0], 0.f), rh0a, rl0a);
            split_bf16(fmaxf(o[1], 0.f), rh0b, rl0b);
            split_bf16(fmaxf(o[2], 0.f), rh1a, rl1a);
            split_bf16(fmaxf(o[3], 0.f), rh1b, rl1b);
            *(__nv_bfloat162*)&g_h1rh[nxt][(size_t)R0 * HID + j0] = __halves2bfloat162(rh0a, rh0b);
            *(__nv_bfloat162*)&g_h1rl[nxt][(size_t)R0 * HID + j0] = __halves2bfloat162(rl0a, rl0b);
            *(__nv_bfloat162*)&g_h1rh[nxt][(size_t)R1 * HID + j0] = __halves2bfloat162(rh1a, rh1b);
            *(__nv_bfloat162*)&g_h1rl[nxt][(size_t)R1 * HID + j0] = __halves2bfloat162(rl1a, rl1b);
        }
    }
}

// ---------------------------------------------------------------------------
// Output head as mma-split GEMM: out = sigmoid(relu(h1) @ Wout^T + bout).
// CTA = 64 rows x 32 cols (24 used), K=512, 4 warps, same 4-stage pipeline.
// Grid 16 CTAs, 128 threads.
// ---------------------------------------------------------------------------
__global__ __launch_bounds__(128, 1)
void out_mma_kernel(int cur,
                    const float* __restrict__ bout,
                    float* __restrict__ outputs,
                    int step)
{
    constexpr int NT = HID / KT;   // 32
    const int nxt = cur ^ 1;
    const __nv_bfloat16* __restrict__ Ah = g_h1rh[nxt];
    const __nv_bfloat16* __restrict__ Al = g_h1rl[nxt];

    __shared__ __align__(16) __nv_bfloat16 sA[4][2][64 * AST];
    __shared__ __align__(16) __nv_bfloat16 sW[4][2][32 * AST];

    const int tid  = threadIdx.x;
    const int w    = tid >> 5;
    const int l    = tid & 31;
    const int rowBase = blockIdx.x * 64;

    float cC[4][4];
    #pragma unroll
    for (int nf = 0; nf < 4; nf++)
        #pragma unroll
        for (int i = 0; i < 4; i++) cC[nf][i] = 0.f;

    const int aOff = (w * 16 + (l & 7) + (((l >> 3) & 1) << 3)) * AST + ((l >> 4) << 3);
    const int wOff = ((l & 7) + (((l >> 4) & 1) << 3)) * AST + (((l >> 3) & 1) << 3);

    auto stage = [&](int t) {
        const int buf = t & 3;
        const int koff = t * KT;
        // A: 64 rows x 16, hi+lo = 256 chunks over 128 threads
        #pragma unroll
        for (int i = tid; i < 256; i += 128) {
            const int part = i >> 7;
            const int idx  = i & 127;
            const int arow = idx >> 1;
            const int acol = (idx & 1) << 3;
            const __nv_bfloat16* src = (part ? Al : Ah)
                                     + (size_t)(rowBase + arow) * HID + koff + acol;
            cpa16(smem_u32(&sA[buf][part][arow * AST + acol]), src);
        }
        // W: 32 rows x 16, hi+lo = 128 chunks
        {
            const int part = tid >> 6;
            const int idx  = tid & 63;
            const int rr   = idx >> 1;
            const int cc   = (idx & 1) << 3;
            const __nv_bfloat16* src = (part ? g_woutl : g_wouth)
                                     + (size_t)rr * HID + koff + cc;
            cpa16(smem_u32(&sW[buf][part][rr * AST + cc]), src);
        }
    };

    auto compute = [&](int t) {
        const int buf = t & 3;
        uint32_t ah[4], al[4];
        ldsm4(ah, smem_u32(&sA[buf][0][0]) + aOff * 2);
        ldsm4(al, smem_u32(&sA[buf][1][0]) + aOff * 2);
        uint32_t bh[8], bl[8];
        const uint32_t wbh = smem_u32(&sW[buf][0][0]) + wOff * 2;
        const uint32_t wbl = smem_u32(&sW[buf][1][0]) + wOff * 2;
        ldsm4(bh,     wbh);
        ldsm4(bh + 4, wbh + 16 * AST * 2);
        ldsm4(bl,     wbl);
        ldsm4(bl + 4, wbl + 16 * AST * 2);
        #pragma unroll
        for (int nf = 0; nf < 4; nf++) {
            mma_bf16(cC[nf], ah, bh[2 * nf], bh[2 * nf + 1]);
            mma_bf16(cC[nf], al, bh[2 * nf], bh[2 * nf + 1]);
            mma_bf16(cC[nf], ah, bl[2 * nf], bl[2 * nf + 1]);
        }
    };

    stage(0); cpa_commit();
    stage(1); cpa_commit();
    stage(2); cpa_commit();
    for (int t = 0; t < NT; t++) {
        cpa_wait<2>();
        __syncthreads();
        compute(t);
        if (t + 3 < NT) stage(t + 3);
        cpa_commit();
    }

    // epilogue
    const int g  = l >> 2;
    const int c4 = l & 3;
    const int R0 = rowBase + w * 16 + g;
    const int R1 = R0 + 8;
    #pragma unroll
    for (int nf = 0; nf < 4; nf++) {
        #pragma unroll
        for (int i = 0; i < 4; i++) {
            const int j   = nf * 8 + 2 * c4 + (i & 1);
            const int row = (i < 2) ? R0 : R1;
            if (j < TSZ) {
                const float v = sigf(cC[nf][i] + __ldg(bout + j));
                outputs[(size_t)row * (PLEN * TSZ) + (size_t)step * TSZ + j] = v;
                __nv_bfloat16 vh, vl;
                split_bf16(v, vh, vl);
                g_valh[nxt][row * XP0 + j] = vh;
                g_vall[nxt][row * XP0 + j] = vl;
            }
        }
    }
}

// ---------------------------------------------------------------------------
// init: copy/split initial hidden, zero val buffers, split + pad weights
// ---------------------------------------------------------------------------
__global__ void init_kernel(const float* __restrict__ hidden,
                            const float* __restrict__ Wih0,
                            const float* __restrict__ Whh0,
                            const float* __restrict__ Wih1,
                            const float* __restrict__ Whh1,
                            const float* __restrict__ Wout)
{
    const int i = blockIdx.x * blockDim.x + threadIdx.x;
    const __nv_bfloat16 z16 = __float2bfloat16(0.0f);

    if (i < BATCH * HID) {
        const float a = hidden[i];
        const float b = hidden[BATCH * HID + i];
        g_h0f[0][i] = a;
        g_h1f[0][i] = b;
        split_bf16(a, g_h0h[0][i], g_h0l[0][i]);
        split_bf16(b, g_h1h[0][i], g_h1l[0][i]);
    }
    if (i < 2 * BATCH * XP0) {
        (&g_valh[0][0])[i] = z16;
        (&g_vall[0][0])[i] = z16;
    }
    if (i < 3 * HID * XP0) {
        const int r = i / XP0;
        const int k = i % XP0;
        const float ww = (k < TSZ) ? Wih0[r * TSZ + k] : 0.0f;
        split_bf16(ww, g_w0xh[i], g_w0xl[i]);
    }
    if (i < 32 * HID) {
        const int r = i / HID;
        const int k = i % HID;
        const float ww = (r < TSZ) ? Wout[r * HID + k] : 0.0f;
        split_bf16(ww, g_wouth[i], g_woutl[i]);
    }
    if (i < 3 * HID * HID) {
        split_bf16(Whh0[i], g_w0hh[i], g_w0hl[i]);
        split_bf16(Wih1[i], g_w1xh[i], g_w1xl[i]);
        split_bf16(Whh1[i], g_w1hh[i], g_w1hl[i]);
    }
}

__global__ void fin_kernel(float* __restrict__ dst)
{
    const int i = blockIdx.x * blockDim.x + threadIdx.x;
    if (i < BATCH * HID) {
        dst[i] = g_h0f[0][i];
        dst[BATCH * HID + i] = g_h1f[0][i];
    }
}

// ---------------------------------------------------------------------------
// host
// ---------------------------------------------------------------------------
extern "C" void kernel_launch(void* const* d_in, const int* in_sizes, int n_in,
                              void* d_out, int out_size)
{
    const float* hidden = (const float*)d_in[0];
    const float* Wih0   = (const float*)d_in[1];
    const float* Whh0   = (const float*)d_in[2];
    const float* bih0   = (const float*)d_in[3];
    const float* bhh0   = (const float*)d_in[4];
    const float* Wih1   = (const float*)d_in[5];
    const float* Whh1   = (const float*)d_in[6];
    const float* bih1   = (const float*)d_in[7];
    const float* bhh1   = (const float*)d_in[8];
    const float* Wout   = (const float*)d_in[9];
    const float* bout   = (const float*)d_in[10];
    float* out = (float*)d_out;

    cudaFuncSetAttribute(gru_mma_kernel<0>,
                         cudaFuncAttributeMaxDynamicSharedMemorySize, G_SMEM);
    cudaFuncSetAttribute(gru_mma_kernel<1>,
                         cudaFuncAttributeMaxDynamicSharedMemorySize, G_SMEM);

    init_kernel<<<(3 * HID * HID + 255) / 256, 256>>>(hidden, Wih0, Whh0, Wih1,
                                                      Whh1, Wout);

    const dim3 lgrid(BATCH / TM, HID / TN);   // (8, 16)
    for (int s = 0; s < PLEN; s++) {
        const int cur = s & 1;
        gru_mma_kernel<0><<<lgrid, 256, G_SMEM>>>(cur, bih0, bhh0);
        gru_mma_kernel<1><<<lgrid, 256, G_SMEM>>>(cur, bih1, bhh1);
        out_mma_kernel<<<BATCH / 64, 128>>>(cur, bout, out, s);
    }
    fin_kernel<<<(BATCH * HID + 255) / 256, 256>>>(out + (size_t)BATCH * PLEN * TSZ);
}

// round 9
// speedup vs baseline: 2.2847x; 1.0487x over previous
#include <cuda_runtime.h>
#include <cuda_bf16.h>
#include <cstdint>

// Problem constants
#define BATCH 1024
#define HID   512
#define TSZ   24
#define PLEN  256
#define XP0   32          // padded layer0 input width (24 -> 32)
#define NCTA  128         // persistent grid size (must be <= SM count)

// GRU layer tile config: CTA-tile = 128 rows x 32 gate-cols, 8 warps
#define TM 128
#define TN 32
#define KT 16             // k per tile
#define AST 24            // smem row stride (bf16 elems)

// dynamic smem layout (bytes)
#define G_APART 6144              // one A part: 128*24*2
#define G_WPART 4608              // one W part: 96*24*2
#define G_STAGE (2*G_APART + 2*G_WPART)   // 21504
#define G_SMEM  (4*G_STAGE)               // 86016

// ---------------------------------------------------------------------------
// Device state (no allocation allowed -> __device__ globals)
// ---------------------------------------------------------------------------
__device__ float         g_h0f[2][BATCH * HID];
__device__ float         g_h1f[2][BATCH * HID];
__device__ __nv_bfloat16 g_h0h[2][BATCH * HID], g_h0l[2][BATCH * HID];
__device__ __nv_bfloat16 g_h1h[2][BATCH * HID], g_h1l[2][BATCH * HID];
__device__ __nv_bfloat16 g_valh[2][BATCH * XP0], g_vall[2][BATCH * XP0];
__device__ __nv_bfloat16 g_w0xh[3 * HID * XP0], g_w0xl[3 * HID * XP0];
__device__ __nv_bfloat16 g_w0hh[3 * HID * HID], g_w0hl[3 * HID * HID];
__device__ __nv_bfloat16 g_w1xh[3 * HID * HID], g_w1xl[3 * HID * HID];
__device__ __nv_bfloat16 g_w1hh[3 * HID * HID], g_w1hl[3 * HID * HID];
__device__ unsigned      g_barcnt;

// ---------------------------------------------------------------------------
// helpers
// ---------------------------------------------------------------------------
__device__ __forceinline__ float sigf(float x) { return 1.0f / (1.0f + __expf(-x)); }
__device__ __forceinline__ float tanhf_fast(float x) {
    return 1.0f - 2.0f / (__expf(2.0f * x) + 1.0f);
}

__device__ __forceinline__ uint32_t smem_u32(const void* p) {
    uint32_t a;
    asm("{ .reg .u64 t; cvta.to.shared.u64 t, %1; cvt.u32.u64 %0, t; }" : "=r"(a) : "l"(p));
    return a;
}

__device__ __forceinline__ void cpa16(uint32_t dst, const void* src) {
    asm volatile("cp.async.cg.shared.global [%0], [%1], 16;" :: "r"(dst), "l"(src) : "memory");
}
__device__ __forceinline__ void cpa_commit() {
    asm volatile("cp.async.commit_group;" ::: "memory");
}
template<int N>
__device__ __forceinline__ void cpa_wait() {
    asm volatile("cp.async.wait_group %0;" :: "n"(N) : "memory");
}

__device__ __forceinline__ void ldsm4(uint32_t* r, uint32_t addr) {
    asm volatile("ldmatrix.sync.aligned.m8n8.x4.shared.b16 {%0,%1,%2,%3}, [%4];"
                 : "=r"(r[0]), "=r"(r[1]), "=r"(r[2]), "=r"(r[3]) : "r"(addr));
}

__device__ __forceinline__ void mma_bf16(float* c, const uint32_t* a,
                                         uint32_t b0, uint32_t b1) {
    asm volatile(
        "mma.sync.aligned.m16n8k16.row.col.f32.bf16.bf16.f32 "
        "{%0,%1,%2,%3}, {%4,%5,%6,%7}, {%8,%9}, {%0,%1,%2,%3};"
        : "+f"(c[0]), "+f"(c[1]), "+f"(c[2]), "+f"(c[3])
        : "r"(a[0]), "r"(a[1]), "r"(a[2]), "r"(a[3]), "r"(b0), "r"(b1));
}

__device__ __forceinline__ void split_bf16(float x, __nv_bfloat16& h, __nv_bfloat16& l) {
    h = __float2bfloat16(x);
    l = __float2bfloat16(x - __bfloat162float(h));
}

// Software grid barrier: monotone counter, release/acquire semantics.
// All cross-CTA data is read via cp.async.cg / __ldcg / ld.acquire (L1-bypass),
// so L2 is the coherence point.
__device__ __forceinline__ void grid_barrier(unsigned target) {
    __threadfence();            // order this thread's global stores (release)
    __syncthreads();
    if (threadIdx.x == 0) {
        atomicAdd(&g_barcnt, 1u);
        unsigned v;
        do {
            asm volatile("ld.acquire.gpu.global.u32 %0, [%1];"
                         : "=r"(v) : "l"(&g_barcnt));
            if (v < target) __nanosleep(64);
        } while (v < target);
    }
    __syncthreads();
}

// ---------------------------------------------------------------------------
// GRU layer step (device function): mma.sync bf16-split, 4-stage cp.async
// pipeline, 1 barrier per tile. CTA id -> (bx = id%8 row-block, by = id/8
// col-block). LAYER=0: x=val[cur](K=32), h=h0[cur]->h0[nxt].
// LAYER=1: x=h0[nxt](K=512), h=h1[cur]->h1[nxt].
// ---------------------------------------------------------------------------
template<int LAYER>
__device__ __forceinline__ void gru_layer_step(char* sm, int cur,
                                               const float* __restrict__ bih,
                                               const float* __restrict__ bhh)
{
    constexpr int KX  = (LAYER == 0) ? XP0 : HID;
    constexpr int NXT = KX / KT;
    constexpr int NT  = NXT + HID / KT;
    const int nxt = cur ^ 1;

    const __nv_bfloat16* __restrict__ xh = (LAYER == 0) ? g_valh[cur] : g_h0h[nxt];
    const __nv_bfloat16* __restrict__ xl = (LAYER == 0) ? g_vall[cur] : g_h0l[nxt];
    const __nv_bfloat16* __restrict__ hh = (LAYER == 0) ? g_h0h[cur] : g_h1h[cur];
    const __nv_bfloat16* __restrict__ hl = (LAYER == 0) ? g_h0l[cur] : g_h1l[cur];
    const float* __restrict__ hinf       = (LAYER == 0) ? g_h0f[cur] : g_h1f[cur];
    float* __restrict__ houtf            = (LAYER == 0) ? g_h0f[nxt] : g_h1f[nxt];
    __nv_bfloat16* __restrict__ houth    = (LAYER == 0) ? g_h0h[nxt] : g_h1h[nxt];
    __nv_bfloat16* __restrict__ houtl    = (LAYER == 0) ? g_h0l[nxt] : g_h1l[nxt];
    const __nv_bfloat16* __restrict__ Wxh  = (LAYER == 0) ? g_w0xh : g_w1xh;
    const __nv_bfloat16* __restrict__ Wxl  = (LAYER == 0) ? g_w0xl : g_w1xl;
    const __nv_bfloat16* __restrict__ Whhh = (LAYER == 0) ? g_w0hh : g_w1hh;
    const __nv_bfloat16* __restrict__ Whhl = (LAYER == 0) ? g_w0hl : g_w1hl;

    auto sAp = [&](int s, int part) -> char* { return sm + s * G_STAGE + part * G_APART; };
    auto sWp = [&](int s, int part) -> char* {
        return sm + s * G_STAGE + 2 * G_APART + part * G_WPART;
    };

    const int tid  = threadIdx.x;
    const int w    = tid >> 5;
    const int l    = tid & 31;
    const int rowBase = (blockIdx.x & 7) * TM;
    const int colBase = (blockIdx.x >> 3) * TN;

    // accumulators: [plane r,z,inn,hn][nf][reg]
    float cA[4][4][4];
    {
        const int c4 = l & 3;
        #pragma unroll
        for (int nf = 0; nf < 4; nf++) {
            const int j0 = colBase + nf * 8 + 2 * c4;
            const float br0 = __ldg(bih + j0)     + __ldg(bhh + j0);
            const float br1 = __ldg(bih + j0 + 1) + __ldg(bhh + j0 + 1);
            const float bz0 = __ldg(bih + HID + j0)     + __ldg(bhh + HID + j0);
            const float bz1 = __ldg(bih + HID + j0 + 1) + __ldg(bhh + HID + j0 + 1);
            const float bi0 = __ldg(bih + 2 * HID + j0);
            const float bi1 = __ldg(bih + 2 * HID + j0 + 1);
            const float bn0 = __ldg(bhh + 2 * HID + j0);
            const float bn1 = __ldg(bhh + 2 * HID + j0 + 1);
            cA[0][nf][0] = br0; cA[0][nf][1] = br1; cA[0][nf][2] = br0; cA[0][nf][3] = br1;
            cA[1][nf][0] = bz0; cA[1][nf][1] = bz1; cA[1][nf][2] = bz0; cA[1][nf][3] = bz1;
            cA[2][nf][0] = bi0; cA[2][nf][1] = bi1; cA[2][nf][2] = bi0; cA[2][nf][3] = bi1;
            cA[3][nf][0] = bn0; cA[3][nf][1] = bn1; cA[3][nf][2] = bn0; cA[3][nf][3] = bn1;
        }
    }

    const int aOff = (w * 16 + (l & 7) + (((l >> 3) & 1) << 3)) * AST + ((l >> 4) << 3);
    const int wOff = ((l & 7) + (((l >> 4) & 1) << 3)) * AST + (((l >> 3) & 1) << 3);

    const int ar = tid >> 1;            // A row 0..127
    const int ac = (tid & 1) << 3;      // k-half offset (elems)

    auto stage = [&](int t) {
        const int buf = t & 3;
        const bool xph = (t < NXT);
        const __nv_bfloat16* Ah = xph ? xh : hh;
        const __nv_bfloat16* Al = xph ? xl : hl;
        const __nv_bfloat16* Wh = xph ? Wxh : Whhh;
        const __nv_bfloat16* Wl = xph ? Wxl : Whhl;
        const int K    = xph ? KX : HID;
        const int koff = (xph ? t : t - NXT) * KT;

        {
            const size_t g = (size_t)(rowBase + ar) * K + koff + ac;
            cpa16(smem_u32(sAp(buf, 0) + (ar * AST + ac) * 2), Ah + g);
            cpa16(smem_u32(sAp(buf, 1) + (ar * AST + ac) * 2), Al + g);
        }
        #pragma unroll
        for (int i = tid; i < 384; i += 256) {
            const int part = i / 192;
            const int idx  = i % 192;
            const int rr   = idx >> 1;
            const int cc   = (idx & 1) << 3;
            const int grow = (rr >> 5) * HID + colBase + (rr & 31);
            const __nv_bfloat16* src = (part ? Wl : Wh) + (size_t)grow * K + koff + cc;
            cpa16(smem_u32(sWp(buf, part) + (rr * AST + cc) * 2), src);
        }
    };

    auto compute = [&](int t) {
        const int buf = t & 3;
        const bool xph = (t < NXT);
        uint32_t ah[4], al[4];
        ldsm4(ah, smem_u32(sAp(buf, 0)) + aOff * 2);
        ldsm4(al, smem_u32(sAp(buf, 1)) + aOff * 2);

        const uint32_t wbh = smem_u32(sWp(buf, 0)) + wOff * 2;
        const uint32_t wbl = smem_u32(sWp(buf, 1)) + wOff * 2;

        #pragma unroll
        for (int p = 0; p < 3; p++) {
            uint32_t bh[8], bl[8];
            ldsm4(bh,     wbh + (p * 32) * AST * 2);
            ldsm4(bh + 4, wbh + (p * 32 + 16) * AST * 2);
            ldsm4(bl,     wbl + (p * 32) * AST * 2);
            ldsm4(bl + 4, wbl + (p * 32 + 16) * AST * 2);
            float (*C)[4] = (p == 2) ? (xph ? cA[2] : cA[3]) : cA[p];
            #pragma unroll
            for (int nf = 0; nf < 4; nf++) {
                mma_bf16(C[nf], ah, bh[2 * nf], bh[2 * nf + 1]);
                mma_bf16(C[nf], al, bh[2 * nf], bh[2 * nf + 1]);
                mma_bf16(C[nf], ah, bl[2 * nf], bl[2 * nf + 1]);
            }
        }
    };

    stage(0); cpa_commit();
    stage(1); cpa_commit();
    stage(2); cpa_commit();
    for (int t = 0; t < NT; t++) {
        cpa_wait<2>();
        __syncthreads();
        compute(t);
        if (t + 3 < NT) stage(t + 3);
        cpa_commit();
    }

    // GRU epilogue (hinf via __ldcg: L2-coherent cross-CTA reads)
    const int g  = l >> 2;
    const int c4 = l & 3;
    const int R0 = rowBase + w * 16 + g;
    const int R1 = R0 + 8;
    #pragma unroll
    for (int nf = 0; nf < 4; nf++) {
        const int j0 = colBase + nf * 8 + 2 * c4;
        const float2 h0v = __ldcg((const float2*)(hinf + (size_t)R0 * HID + j0));
        const float2 h1v = __ldcg((const float2*)(hinf + (size_t)R1 * HID + j0));
        float o[4];
        const float hvv[4] = { h0v.x, h0v.y, h1v.x, h1v.y };
        #pragma unroll
        for (int i = 0; i < 4; i++) {
            const float r_ = sigf(cA[0][nf][i]);
            const float z_ = sigf(cA[1][nf][i]);
            const float n_ = tanhf_fast(cA[2][nf][i] + r_ * cA[3][nf][i]);
            o[i] = (1.0f - z_) * n_ + z_ * hvv[i];
        }
        *(float2*)&houtf[(size_t)R0 * HID + j0] = make_float2(o[0], o[1]);
        *(float2*)&houtf[(size_t)R1 * HID + j0] = make_float2(o[2], o[3]);
        __nv_bfloat16 h0a, l0a, h0b, l0b, h1a, l1a, h1b, l1b;
        split_bf16(o[0], h0a, l0a); split_bf16(o[1], h0b, l0b);
        split_bf16(o[2], h1a, l1a); split_bf16(o[3], h1b, l1b);
        *(__nv_bfloat162*)&houth[(size_t)R0 * HID + j0] = __halves2bfloat162(h0a, h0b);
        *(__nv_bfloat162*)&houtl[(size_t)R0 * HID + j0] = __halves2bfloat162(l0a, l0b);
        *(__nv_bfloat162*)&houth[(size_t)R1 * HID + j0] = __halves2bfloat162(h1a, h1b);
        *(__nv_bfloat162*)&houtl[(size_t)R1 * HID + j0] = __halves2bfloat162(l1a, l1b);
    }
}

// ---------------------------------------------------------------------------
// Output head (device function): warp-per-row, Wout/bias L1-hot across steps.
// ---------------------------------------------------------------------------
__device__ __forceinline__ void head_step(int cur,
                                          const float* __restrict__ Wout,
                                          const float* __restrict__ bout,
                                          float* __restrict__ outputs, int step)
{
    const int nxt  = cur ^ 1;
    const int w    = threadIdx.x >> 5;
    const int lane = threadIdx.x & 31;
    const int row  = blockIdx.x * 8 + w;
    const float* __restrict__ h1 = g_h1f[nxt];

    float xv[16];
    {
        const float4* hr = (const float4*)(h1 + (size_t)row * HID);
        #pragma unroll
        for (int q = 0; q < 4; q++) {
            float4 v = __ldcg(&hr[lane * 4 + q]);
            xv[q * 4 + 0] = fmaxf(v.x, 0.f);
            xv[q * 4 + 1] = fmaxf(v.y, 0.f);
            xv[q * 4 + 2] = fmaxf(v.z, 0.f);
            xv[q * 4 + 3] = fmaxf(v.w, 0.f);
        }
    }

    float s[TSZ];
    #pragma unroll
    for (int j = 0; j < TSZ; j++) {
        const float4* wr = (const float4*)(Wout + (size_t)j * HID + lane * 16);
        float a = 0.f;
        #pragma unroll
        for (int q = 0; q < 4; q++) {
            const float4 wv = __ldg(&wr[q]);
            a = fmaf(xv[q * 4 + 0], wv.x, a);
            a = fmaf(xv[q * 4 + 1], wv.y, a);
            a = fmaf(xv[q * 4 + 2], wv.z, a);
            a = fmaf(xv[q * 4 + 3], wv.w, a);
        }
        s[j] = a;
    }

    #pragma unroll
    for (int off = 16; off >= 1; off >>= 1) {
        #pragma unroll
        for (int j = 0; j < TSZ; j++)
            s[j] += __shfl_xor_sync(0xFFFFFFFFu, s[j], off);
    }

    if (lane < TSZ) {
        const float v = sigf(s[lane] + __ldg(bout + lane));
        outputs[(size_t)row * (PLEN * TSZ) + (size_t)step * TSZ + lane] = v;
        __nv_bfloat16 vh, vl;
        split_bf16(v, vh, vl);
        g_valh[nxt][row * XP0 + lane] = vh;
        g_vall[nxt][row * XP0 + lane] = vl;
    }
}

// ---------------------------------------------------------------------------
// Persistent whole-rollout kernel: 128 CTAs, 3 grid barriers per step.
// ---------------------------------------------------------------------------
__global__ __launch_bounds__(256, 1)
void decoder_persistent(const float* __restrict__ bih0, const float* __restrict__ bhh0,
                        const float* __restrict__ bih1, const float* __restrict__ bhh1,
                        const float* __restrict__ Wout, const float* __restrict__ bout,
                        float* __restrict__ out)
{
    extern __shared__ __align__(16) char sm[];
    unsigned target = 0;

    for (int s = 0; s < PLEN; s++) {
        const int cur = s & 1;
        gru_layer_step<0>(sm, cur, bih0, bhh0);
        target += NCTA; grid_barrier(target);
        gru_layer_step<1>(sm, cur, bih1, bhh1);
        target += NCTA; grid_barrier(target);
        head_step(cur, Wout, bout, out, s);
        target += NCTA; grid_barrier(target);
    }

    // final hidden copy: after 256 steps (even), state sits in buffer 0
    constexpr int CH = BATCH * HID / NCTA;   // 4096
    const int base = blockIdx.x * CH;
    float* dst = out + (size_t)BATCH * PLEN * TSZ;
    for (int i = threadIdx.x; i < CH; i += blockDim.x) {
        dst[base + i]              = __ldcg(&g_h0f[0][base + i]);
        dst[BATCH * HID + base + i] = __ldcg(&g_h1f[0][base + i]);
    }
}

// ---------------------------------------------------------------------------
// init: reset barrier, copy/split initial hidden, zero val, split weights
// ---------------------------------------------------------------------------
__global__ void init_kernel(const float* __restrict__ hidden,
                            const float* __restrict__ Wih0,
                            const float* __restrict__ Whh0,
                            const float* __restrict__ Wih1,
                            const float* __restrict__ Whh1)
{
    const int i = blockIdx.x * blockDim.x + threadIdx.x;
    const __nv_bfloat16 z16 = __float2bfloat16(0.0f);

    if (i == 0) g_barcnt = 0;

    if (i < BATCH * HID) {
        const float a = hidden[i];
        const float b = hidden[BATCH * HID + i];
        g_h0f[0][i] = a;
        g_h1f[0][i] = b;
        split_bf16(a, g_h0h[0][i], g_h0l[0][i]);
        split_bf16(b, g_h1h[0][i], g_h1l[0][i]);
    }
    if (i < 2 * BATCH * XP0) {
        (&g_valh[0][0])[i] = z16;
        (&g_vall[0][0])[i] = z16;
    }
    if (i < 3 * HID * XP0) {
        const int r = i / XP0;
        const int k = i % XP0;
        const float ww = (k < TSZ) ? Wih0[r * TSZ + k] : 0.0f;
        split_bf16(ww, g_w0xh[i], g_w0xl[i]);
    }
    if (i < 3 * HID * HID) {
        split_bf16(Whh0[i], g_w0hh[i], g_w0hl[i]);
        split_bf16(Wih1[i], g_w1xh[i], g_w1xl[i]);
        split_bf16(Whh1[i], g_w1hh[i], g_w1hl[i]);
    }
}

// ---------------------------------------------------------------------------
// host
// ---------------------------------------------------------------------------
extern "C" void kernel_launch(void* const* d_in, const int* in_sizes, int n_in,
                              void* d_out, int out_size)
{
    const float* hidden = (const float*)d_in[0];
    const float* Wih0   = (const float*)d_in[1];
    const float* Whh0   = (const float*)d_in[2];
    const float* bih0   = (const float*)d_in[3];
    const float* bhh0   = (const float*)d_in[4];
    const float* Wih1   = (const float*)d_in[5];
    const float* Whh1   = (const float*)d_in[6];
    const float* bih1   = (const float*)d_in[7];
    const float* bhh1   = (const float*)d_in[8];
    const float* Wout   = (const float*)d_in[9];
    const float* bout   = (const float*)d_in[10];
    float* out = (float*)d_out;

    cudaFuncSetAttribute(decoder_persistent,
                         cudaFuncAttributeMaxDynamicSharedMemorySize, G_SMEM);

    init_kernel<<<(3 * HID * HID + 255) / 256, 256>>>(hidden, Wih0, Whh0, Wih1, Whh1);
    decoder_persistent<<<NCTA, 256, G_SMEM>>>(bih0, bhh0, bih1, bhh1, Wout, bout, out);
}

// round 10
// speedup vs baseline: 2.4471x; 1.0710x over previous
#include <cuda_runtime.h>
#include <cuda_bf16.h>
#include <cstdint>

// Problem constants
#define BATCH 1024
#define HID   512
#define TSZ   24
#define PLEN  256
#define XP0   32          // padded layer0 input width (24 -> 32)
#define NCTA  256         // persistent grid (2 CTAs/SM co-resident)

// GRU layer tile config: CTA-tile = 64 rows x 32 gate-cols, 8 warps
#define TM 64
#define TN 32
#define KT 16             // k per tile
#define AST 24            // smem row stride (bf16 elems)

// dynamic smem layout (bytes)
#define G_APART 3072              // one A part: 64*24*2
#define G_WPART 4608              // one W part: 96*24*2
#define G_STAGE (2*G_APART + 2*G_WPART)   // 15360
#define G_SMEM  (4*G_STAGE)               // 61440

// ---------------------------------------------------------------------------
// Device state (no allocation allowed -> __device__ globals)
// ---------------------------------------------------------------------------
__device__ float         g_h0f[2][BATCH * HID];
__device__ float         g_h1f[2][BATCH * HID];
__device__ __nv_bfloat16 g_h0h[2][BATCH * HID], g_h0l[2][BATCH * HID];
__device__ __nv_bfloat16 g_h1h[2][BATCH * HID], g_h1l[2][BATCH * HID];
__device__ __nv_bfloat16 g_valh[2][BATCH * XP0], g_vall[2][BATCH * XP0];
__device__ __nv_bfloat16 g_w0xh[3 * HID * XP0], g_w0xl[3 * HID * XP0];
__device__ __nv_bfloat16 g_w0hh[3 * HID * HID], g_w0hl[3 * HID * HID];
__device__ __nv_bfloat16 g_w1xh[3 * HID * HID], g_w1xl[3 * HID * HID];
__device__ __nv_bfloat16 g_w1hh[3 * HID * HID], g_w1hl[3 * HID * HID];
__device__ unsigned      g_barcnt;

// ---------------------------------------------------------------------------
// helpers
// ---------------------------------------------------------------------------
__device__ __forceinline__ float sigf(float x) { return 1.0f / (1.0f + __expf(-x)); }
__device__ __forceinline__ float tanhf_fast(float x) {
    return 1.0f - 2.0f / (__expf(2.0f * x) + 1.0f);
}

__device__ __forceinline__ uint32_t smem_u32(const void* p) {
    uint32_t a;
    asm("{ .reg .u64 t; cvta.to.shared.u64 t, %1; cvt.u32.u64 %0, t; }" : "=r"(a) : "l"(p));
    return a;
}

__device__ __forceinline__ void cpa16(uint32_t dst, const void* src) {
    asm volatile("cp.async.cg.shared.global [%0], [%1], 16;" :: "r"(dst), "l"(src) : "memory");
}
__device__ __forceinline__ void cpa_commit() {
    asm volatile("cp.async.commit_group;" ::: "memory");
}
template<int N>
__device__ __forceinline__ void cpa_wait() {
    asm volatile("cp.async.wait_group %0;" :: "n"(N) : "memory");
}

__device__ __forceinline__ void ldsm4(uint32_t* r, uint32_t addr) {
    asm volatile("ldmatrix.sync.aligned.m8n8.x4.shared.b16 {%0,%1,%2,%3}, [%4];"
                 : "=r"(r[0]), "=r"(r[1]), "=r"(r[2]), "=r"(r[3]) : "r"(addr));
}

__device__ __forceinline__ void mma_bf16(float* c, const uint32_t* a,
                                         uint32_t b0, uint32_t b1) {
    asm volatile(
        "mma.sync.aligned.m16n8k16.row.col.f32.bf16.bf16.f32 "
        "{%0,%1,%2,%3}, {%4,%5,%6,%7}, {%8,%9}, {%0,%1,%2,%3};"
        : "+f"(c[0]), "+f"(c[1]), "+f"(c[2]), "+f"(c[3])
        : "r"(a[0]), "r"(a[1]), "r"(a[2]), "r"(a[3]), "r"(b0), "r"(b1));
}

__device__ __forceinline__ void split_bf16(float x, __nv_bfloat16& h, __nv_bfloat16& l) {
    h = __float2bfloat16(x);
    l = __float2bfloat16(x - __bfloat162float(h));
}

// Software grid barrier: monotone counter, release/acquire semantics.
// All cross-CTA data is read via cp.async.cg / __ldcg (L1-bypass), L2-coherent.
__device__ __forceinline__ void grid_barrier(unsigned target) {
    __threadfence();
    __syncthreads();
    if (threadIdx.x == 0) {
        atomicAdd(&g_barcnt, 1u);
        unsigned v;
        do {
            asm volatile("ld.acquire.gpu.global.u32 %0, [%1];"
                         : "=r"(v) : "l"(&g_barcnt));
            if (v < target) __nanosleep(64);
        } while (v < target);
    }
    __syncthreads();
}

// ---------------------------------------------------------------------------
// GRU layer step: CTA = 64 rows x 32 cols; warp = 16 rows x 16 cols
// (rg = w&3 row-group, ch = w>>2 col-half). 32 accum regs/thread.
// CTA id: rowBlk = id & 15, colBlk = id >> 4.
// ---------------------------------------------------------------------------
template<int LAYER>
__device__ __forceinline__ void gru_layer_step(char* sm, int cur,
                                               const float* __restrict__ bih,
                                               const float* __restrict__ bhh)
{
    constexpr int KX  = (LAYER == 0) ? XP0 : HID;
    constexpr int NXT = KX / KT;
    constexpr int NT  = NXT + HID / KT;
    const int nxt = cur ^ 1;

    const __nv_bfloat16* __restrict__ xh = (LAYER == 0) ? g_valh[cur] : g_h0h[nxt];
    const __nv_bfloat16* __restrict__ xl = (LAYER == 0) ? g_vall[cur] : g_h0l[nxt];
    const __nv_bfloat16* __restrict__ hh = (LAYER == 0) ? g_h0h[cur] : g_h1h[cur];
    const __nv_bfloat16* __restrict__ hl = (LAYER == 0) ? g_h0l[cur] : g_h1l[cur];
    const float* __restrict__ hinf       = (LAYER == 0) ? g_h0f[cur] : g_h1f[cur];
    float* __restrict__ houtf            = (LAYER == 0) ? g_h0f[nxt] : g_h1f[nxt];
    __nv_bfloat16* __restrict__ houth    = (LAYER == 0) ? g_h0h[nxt] : g_h1h[nxt];
    __nv_bfloat16* __restrict__ houtl    = (LAYER == 0) ? g_h0l[nxt] : g_h1l[nxt];
    const __nv_bfloat16* __restrict__ Wxh  = (LAYER == 0) ? g_w0xh : g_w1xh;
    const __nv_bfloat16* __restrict__ Wxl  = (LAYER == 0) ? g_w0xl : g_w1xl;
    const __nv_bfloat16* __restrict__ Whhh = (LAYER == 0) ? g_w0hh : g_w1hh;
    const __nv_bfloat16* __restrict__ Whhl = (LAYER == 0) ? g_w0hl : g_w1hl;

    auto sAp = [&](int s, int part) -> char* { return sm + s * G_STAGE + part * G_APART; };
    auto sWp = [&](int s, int part) -> char* {
        return sm + s * G_STAGE + 2 * G_APART + part * G_WPART;
    };

    const int tid  = threadIdx.x;
    const int w    = tid >> 5;
    const int l    = tid & 31;
    const int rg   = w & 3;           // row group: rows rg*16 .. rg*16+15
    const int ch   = w >> 2;          // col half: cols ch*16 .. ch*16+15
    const int rowBase = (blockIdx.x & 15) * TM;
    const int colBase = (blockIdx.x >> 4) * TN;

    // accumulators: [plane r,z,inn,hn][nf(2)][reg(4)] = 32 regs
    float cA[4][2][4];
    {
        const int c4 = l & 3;
        #pragma unroll
        for (int nf = 0; nf < 2; nf++) {
            const int j0 = colBase + ch * 16 + nf * 8 + 2 * c4;
            const float br0 = __ldg(bih + j0)     + __ldg(bhh + j0);
            const float br1 = __ldg(bih + j0 + 1) + __ldg(bhh + j0 + 1);
            const float bz0 = __ldg(bih + HID + j0)     + __ldg(bhh + HID + j0);
            const float bz1 = __ldg(bih + HID + j0 + 1) + __ldg(bhh + HID + j0 + 1);
            const float bi0 = __ldg(bih + 2 * HID + j0);
            const float bi1 = __ldg(bih + 2 * HID + j0 + 1);
            const float bn0 = __ldg(bhh + 2 * HID + j0);
            const float bn1 = __ldg(bhh + 2 * HID + j0 + 1);
            cA[0][nf][0] = br0; cA[0][nf][1] = br1; cA[0][nf][2] = br0; cA[0][nf][3] = br1;
            cA[1][nf][0] = bz0; cA[1][nf][1] = bz1; cA[1][nf][2] = bz0; cA[1][nf][3] = bz1;
            cA[2][nf][0] = bi0; cA[2][nf][1] = bi1; cA[2][nf][2] = bi0; cA[2][nf][3] = bi1;
            cA[3][nf][0] = bn0; cA[3][nf][1] = bn1; cA[3][nf][2] = bn0; cA[3][nf][3] = bn1;
        }
    }

    // ldmatrix lane offsets (bf16-element offsets)
    const int aOff = (rg * 16 + (l & 7) + (((l >> 3) & 1) << 3)) * AST + ((l >> 4) << 3);
    const int wOff = (ch * 16 + (l & 7) + (((l >> 4) & 1) << 3)) * AST + (((l >> 3) & 1) << 3);

    auto stage = [&](int t) {
        const int buf = t & 3;
        const bool xph = (t < NXT);
        const __nv_bfloat16* Ah = xph ? xh : hh;
        const __nv_bfloat16* Al = xph ? xl : hl;
        const __nv_bfloat16* Wh = xph ? Wxh : Whhh;
        const __nv_bfloat16* Wl = xph ? Wxl : Whhl;
        const int K    = xph ? KX : HID;
        const int koff = (xph ? t : t - NXT) * KT;

        // A: 64 rows x 16 (hi+lo) = 256 chunks over 256 threads
        {
            const int part = tid >> 7;
            const int idx  = tid & 127;
            const int arow = idx >> 1;
            const int acol = (idx & 1) << 3;
            const __nv_bfloat16* src = (part ? Al : Ah)
                                     + (size_t)(rowBase + arow) * K + koff + acol;
            cpa16(smem_u32(sAp(buf, part) + (arow * AST + acol) * 2), src);
        }
        // W: 96 rows x 16 (hi+lo) = 384 chunks
        #pragma unroll
        for (int i = tid; i < 384; i += 256) {
            const int part = i / 192;
            const int idx  = i % 192;
            const int rr   = idx >> 1;
            const int cc   = (idx & 1) << 3;
            const int grow = (rr >> 5) * HID + colBase + (rr & 31);
            const __nv_bfloat16* src = (part ? Wl : Wh) + (size_t)grow * K + koff + cc;
            cpa16(smem_u32(sWp(buf, part) + (rr * AST + cc) * 2), src);
        }
    };

    auto compute = [&](int t) {
        const int buf = t & 3;
        const bool xph = (t < NXT);
        uint32_t ah[4], al[4];
        ldsm4(ah, smem_u32(sAp(buf, 0)) + aOff * 2);
        ldsm4(al, smem_u32(sAp(buf, 1)) + aOff * 2);

        const uint32_t wbh = smem_u32(sWp(buf, 0)) + wOff * 2;
        const uint32_t wbl = smem_u32(sWp(buf, 1)) + wOff * 2;

        #pragma unroll
        for (int p = 0; p < 3; p++) {
            uint32_t bh[4], bl[4];
            ldsm4(bh, wbh + (p * 32) * AST * 2);
            ldsm4(bl, wbl + (p * 32) * AST * 2);
            float (*C)[4] = (p == 2) ? (xph ? cA[2] : cA[3]) : cA[p];
            #pragma unroll
            for (int nf = 0; nf < 2; nf++) {
                mma_bf16(C[nf], ah, bh[2 * nf], bh[2 * nf + 1]);
                mma_bf16(C[nf], al, bh[2 * nf], bh[2 * nf + 1]);
                mma_bf16(C[nf], ah, bl[2 * nf], bl[2 * nf + 1]);
            }
        }
    };

    stage(0); cpa_commit();
    stage(1); cpa_commit();
    stage(2); cpa_commit();
    for (int t = 0; t < NT; t++) {
        cpa_wait<2>();
        __syncthreads();
        compute(t);
        if (t + 3 < NT) stage(t + 3);
        cpa_commit();
    }

    // GRU epilogue (hinf via __ldcg: L2-coherent cross-CTA reads)
    const int g  = l >> 2;
    const int c4 = l & 3;
    const int R0 = rowBase + rg * 16 + g;
    const int R1 = R0 + 8;
    #pragma unroll
    for (int nf = 0; nf < 2; nf++) {
        const int j0 = colBase + ch * 16 + nf * 8 + 2 * c4;
        const float2 h0v = __ldcg((const float2*)(hinf + (size_t)R0 * HID + j0));
        const float2 h1v = __ldcg((const float2*)(hinf + (size_t)R1 * HID + j0));
        float o[4];
        const float hvv[4] = { h0v.x, h0v.y, h1v.x, h1v.y };
        #pragma unroll
        for (int i = 0; i < 4; i++) {
            const float r_ = sigf(cA[0][nf][i]);
            const float z_ = sigf(cA[1][nf][i]);
            const float n_ = tanhf_fast(cA[2][nf][i] + r_ * cA[3][nf][i]);
            o[i] = (1.0f - z_) * n_ + z_ * hvv[i];
        }
        *(float2*)&houtf[(size_t)R0 * HID + j0] = make_float2(o[0], o[1]);
        *(float2*)&houtf[(size_t)R1 * HID + j0] = make_float2(o[2], o[3]);
        __nv_bfloat16 h0a, l0a, h0b, l0b, h1a, l1a, h1b, l1b;
        split_bf16(o[0], h0a, l0a); split_bf16(o[1], h0b, l0b);
        split_bf16(o[2], h1a, l1a); split_bf16(o[3], h1b, l1b);
        *(__nv_bfloat162*)&houth[(size_t)R0 * HID + j0] = __halves2bfloat162(h0a, h0b);
        *(__nv_bfloat162*)&houtl[(size_t)R0 * HID + j0] = __halves2bfloat162(l0a, l0b);
        *(__nv_bfloat162*)&houth[(size_t)R1 * HID + j0] = __halves2bfloat162(h1a, h1b);
        *(__nv_bfloat162*)&houtl[(size_t)R1 * HID + j0] = __halves2bfloat162(l1a, l1b);
    }
}

// ---------------------------------------------------------------------------
// Output head: warp-per-row on CTAs 0..127 (1024 rows), Wout/bias L1-hot.
// ---------------------------------------------------------------------------
__device__ __forceinline__ void head_step(int cur,
                                          const float* __restrict__ Wout,
                                          const float* __restrict__ bout,
                                          float* __restrict__ outputs, int step)
{
    const int nxt  = cur ^ 1;
    const int w    = threadIdx.x >> 5;
    const int lane = threadIdx.x & 31;
    const int row  = blockIdx.x * 8 + w;
    const float* __restrict__ h1 = g_h1f[nxt];

    float xv[16];
    {
        const float4* hr = (const float4*)(h1 + (size_t)row * HID);
        #pragma unroll
        for (int q = 0; q < 4; q++) {
            float4 v = __ldcg(&hr[lane * 4 + q]);
            xv[q * 4 + 0] = fmaxf(v.x, 0.f);
            xv[q * 4 + 1] = fmaxf(v.y, 0.f);
            xv[q * 4 + 2] = fmaxf(v.z, 0.f);
            xv[q * 4 + 3] = fmaxf(v.w, 0.f);
        }
    }

    float s[TSZ];
    #pragma unroll
    for (int j = 0; j < TSZ; j++) {
        const float4* wr = (const float4*)(Wout + (size_t)j * HID + lane * 16);
        float a = 0.f;
        #pragma unroll
        for (int q = 0; q < 4; q++) {
            const float4 wv = __ldg(&wr[q]);
            a = fmaf(xv[q * 4 + 0], wv.x, a);
            a = fmaf(xv[q * 4 + 1], wv.y, a);
            a = fmaf(xv[q * 4 + 2], wv.z, a);
            a = fmaf(xv[q * 4 + 3], wv.w, a);
        }
        s[j] = a;
    }

    #pragma unroll
    for (int off = 16; off >= 1; off >>= 1) {
        #pragma unroll
        for (int j = 0; j < TSZ; j++)
            s[j] += __shfl_xor_sync(0xFFFFFFFFu, s[j], off);
    }

    if (lane < TSZ) {
        const float v = sigf(s[lane] + __ldg(bout + lane));
        outputs[(size_t)row * (PLEN * TSZ) + (size_t)step * TSZ + lane] = v;
        __nv_bfloat16 vh, vl;
        split_bf16(v, vh, vl);
        g_valh[nxt][row * XP0 + lane] = vh;
        g_vall[nxt][row * XP0 + lane] = vl;
    }
}

// ---------------------------------------------------------------------------
// Persistent whole-rollout kernel: 256 CTAs (2/SM), 3 grid barriers per step.
// ---------------------------------------------------------------------------
__global__ __launch_bounds__(256, 2)
void decoder_persistent(const float* __restrict__ bih0, const float* __restrict__ bhh0,
                        const float* __restrict__ bih1, const float* __restrict__ bhh1,
                        const float* __restrict__ Wout, const float* __restrict__ bout,
                        float* __restrict__ out)
{
    extern __shared__ __align__(16) char sm[];
    unsigned target = 0;

    for (int s = 0; s < PLEN; s++) {
        const int cur = s & 1;
        gru_layer_step<0>(sm, cur, bih0, bhh0);
        target += NCTA; grid_barrier(target);
        gru_layer_step<1>(sm, cur, bih1, bhh1);
        target += NCTA; grid_barrier(target);
        if (blockIdx.x < BATCH / 8) head_step(cur, Wout, bout, out, s);
        target += NCTA; grid_barrier(target);
    }

    // final hidden copy: after 256 steps (even), state sits in buffer 0
    constexpr int CH = BATCH * HID / NCTA;   // 2048
    const int base = blockIdx.x * CH;
    float* dst = out + (size_t)BATCH * PLEN * TSZ;
    for (int i = threadIdx.x; i < CH; i += blockDim.x) {
        dst[base + i]               = __ldcg(&g_h0f[0][base + i]);
        dst[BATCH * HID + base + i] = __ldcg(&g_h1f[0][base + i]);
    }
}

// ---------------------------------------------------------------------------
// init: reset barrier, copy/split initial hidden, zero val, split weights
// ---------------------------------------------------------------------------
__global__ void init_kernel(const float* __restrict__ hidden,
                            const float* __restrict__ Wih0,
                            const float* __restrict__ Whh0,
                            const float* __restrict__ Wih1,
                            const float* __restrict__ Whh1)
{
    const int i = blockIdx.x * blockDim.x + threadIdx.x;
    const __nv_bfloat16 z16 = __float2bfloat16(0.0f);

    if (i == 0) g_barcnt = 0;

    if (i < BATCH * HID) {
        const float a = hidden[i];
        const float b = hidden[BATCH * HID + i];
        g_h0f[0][i] = a;
        g_h1f[0][i] = b;
        split_bf16(a, g_h0h[0][i], g_h0l[0][i]);
        split_bf16(b, g_h1h[0][i], g_h1l[0][i]);
    }
    if (i < 2 * BATCH * XP0) {
        (&g_valh[0][0])[i] = z16;
        (&g_vall[0][0])[i] = z16;
    }
    if (i < 3 * HID * XP0) {
        const int r = i / XP0;
        const int k = i % XP0;
        const float ww = (k < TSZ) ? Wih0[r * TSZ + k] : 0.0f;
        split_bf16(ww, g_w0xh[i], g_w0xl[i]);
    }
    if (i < 3 * HID * HID) {
        split_bf16(Whh0[i], g_w0hh[i], g_w0hl[i]);
        split_bf16(Wih1[i], g_w1xh[i], g_w1xl[i]);
        split_bf16(Whh1[i], g_w1hh[i], g_w1hl[i]);
    }
}

// ---------------------------------------------------------------------------
// host
// ---------------------------------------------------------------------------
extern "C" void kernel_launch(void* const* d_in, const int* in_sizes, int n_in,
                              void* d_out, int out_size)
{
    const float* hidden = (const float*)d_in[0];
    const float* Wih0   = (const float*)d_in[1];
    const float* Whh0   = (const float*)d_in[2];
    const float* bih0   = (const float*)d_in[3];
    const float* bhh0   = (const float*)d_in[4];
    const float* Wih1   = (const float*)d_in[5];
    const float* Whh1   = (const float*)d_in[6];
    const float* bih1   = (const float*)d_in[7];
    const float* bhh1   = (const float*)d_in[8];
    const float* Wout   = (const float*)d_in[9];
    const float* bout   = (const float*)d_in[10];
    float* out = (float*)d_out;

    cudaFuncSetAttribute(decoder_persistent,
                         cudaFuncAttributeMaxDynamicSharedMemorySize, G_SMEM);

    init_kernel<<<(3 * HID * HID + 255) / 256, 256>>>(hidden, Wih0, Whh0, Wih1, Whh1);
    decoder_persistent<<<NCTA, 256, G_SMEM>>>(bih0, bhh0, bih1, bhh1, Wout, bout, out);
}

// round 11
// speedup vs baseline: 2.8152x; 1.1504x over previous
#include <cuda_runtime.h>
#include <cuda_bf16.h>
#include <cstdint>

// Problem constants
#define BATCH 1024
#define HID   512
#define TSZ   24
#define PLEN  256
#define XP0   32          // padded layer0 input width (24 -> 32)
#define NCTA  256         // persistent grid (2 CTAs/SM co-resident)

// GRU layer tile config: CTA-tile = 64 rows x 32 gate-cols, 8 warps
#define TM 64
#define TN 32
#define KT 32             // k per tile
#define AST 40            // smem row stride (bf16 elems): 32 + 8 pad

// dynamic smem layout (bytes)
#define G_APART (64 * AST * 2)            // 5120
#define G_WPART (96 * AST * 2)            // 7680
#define G_STAGE (2*G_APART + 2*G_WPART)   // 25600
#define G_SMEM  (4*G_STAGE)               // 102400

// ---------------------------------------------------------------------------
// Device state (no allocation allowed -> __device__ globals)
// ---------------------------------------------------------------------------
__device__ float         g_h0f[2][BATCH * HID];
__device__ float         g_h1f[2][BATCH * HID];
__device__ __nv_bfloat16 g_h0h[2][BATCH * HID], g_h0l[2][BATCH * HID];
__device__ __nv_bfloat16 g_h1h[2][BATCH * HID], g_h1l[2][BATCH * HID];
__device__ __nv_bfloat16 g_valh[2][BATCH * XP0], g_vall[2][BATCH * XP0];
__device__ __nv_bfloat16 g_w0xh[3 * HID * XP0], g_w0xl[3 * HID * XP0];
__device__ __nv_bfloat16 g_w0hh[3 * HID * HID], g_w0hl[3 * HID * HID];
__device__ __nv_bfloat16 g_w1xh[3 * HID * HID], g_w1xl[3 * HID * HID];
__device__ __nv_bfloat16 g_w1hh[3 * HID * HID], g_w1hl[3 * HID * HID];
__device__ unsigned      g_barcnt;

// ---------------------------------------------------------------------------
// helpers
// ---------------------------------------------------------------------------
__device__ __forceinline__ float sigf(float x) { return 1.0f / (1.0f + __expf(-x)); }
__device__ __forceinline__ float tanhf_fast(float x) {
    return 1.0f - 2.0f / (__expf(2.0f * x) + 1.0f);
}

__device__ __forceinline__ uint32_t smem_u32(const void* p) {
    uint32_t a;
    asm("{ .reg .u64 t; cvta.to.shared.u64 t, %1; cvt.u32.u64 %0, t; }" : "=r"(a) : "l"(p));
    return a;
}

__device__ __forceinline__ void cpa16(uint32_t dst, const void* src) {
    asm volatile("cp.async.cg.shared.global [%0], [%1], 16;" :: "r"(dst), "l"(src) : "memory");
}
__device__ __forceinline__ void cpa_commit() {
    asm volatile("cp.async.commit_group;" ::: "memory");
}
template<int N>
__device__ __forceinline__ void cpa_wait() {
    asm volatile("cp.async.wait_group %0;" :: "n"(N) : "memory");
}

__device__ __forceinline__ void ldsm4(uint32_t* r, uint32_t addr) {
    asm volatile("ldmatrix.sync.aligned.m8n8.x4.shared.b16 {%0,%1,%2,%3}, [%4];"
                 : "=r"(r[0]), "=r"(r[1]), "=r"(r[2]), "=r"(r[3]) : "r"(addr));
}

__device__ __forceinline__ void mma_bf16(float* c, const uint32_t* a,
                                         uint32_t b0, uint32_t b1) {
    asm volatile(
        "mma.sync.aligned.m16n8k16.row.col.f32.bf16.bf16.f32 "
        "{%0,%1,%2,%3}, {%4,%5,%6,%7}, {%8,%9}, {%0,%1,%2,%3};"
        : "+f"(c[0]), "+f"(c[1]), "+f"(c[2]), "+f"(c[3])
        : "r"(a[0]), "r"(a[1]), "r"(a[2]), "r"(a[3]), "r"(b0), "r"(b1));
}

__device__ __forceinline__ void split_bf16(float x, __nv_bfloat16& h, __nv_bfloat16& l) {
    h = __float2bfloat16(x);
    l = __float2bfloat16(x - __bfloat162float(h));
}

// Software grid barrier: monotone counter, release/acquire semantics.
// All cross-CTA data is read via cp.async.cg / __ldcg (L1-bypass), L2-coherent.
__device__ __forceinline__ void grid_barrier(unsigned target) {
    __threadfence();
    __syncthreads();
    if (threadIdx.x == 0) {
        atomicAdd(&g_barcnt, 1u);
        unsigned v;
        do {
            asm volatile("ld.acquire.gpu.global.u32 %0, [%1];"
                         : "=r"(v) : "l"(&g_barcnt));
            if (v < target) __nanosleep(64);
        } while (v < target);
    }
    __syncthreads();
}

// ---------------------------------------------------------------------------
// GRU layer step: CTA = 64 rows x 32 cols; warp = 16 rows x 16 cols.
// KT=32 tiles, pow2 loader mappings, per-thread offsets hoisted.
// CTA id: rowBlk = id & 15, colBlk = id >> 4.
// ---------------------------------------------------------------------------
template<int LAYER>
__device__ __forceinline__ void gru_layer_step(char* sm, int cur,
                                               const float* __restrict__ bih,
                                               const float* __restrict__ bhh)
{
    constexpr int KPH0 = (LAYER == 0) ? XP0 : HID;
    constexpr int NXT  = KPH0 / KT;            // 1 or 16
    constexpr int NT   = NXT + HID / KT;       // 17 or 32
    const int nxt = cur ^ 1;

    const __nv_bfloat16* __restrict__ xh = (LAYER == 0) ? g_valh[cur] : g_h0h[nxt];
    const __nv_bfloat16* __restrict__ xl = (LAYER == 0) ? g_vall[cur] : g_h0l[nxt];
    const __nv_bfloat16* __restrict__ hh = (LAYER == 0) ? g_h0h[cur] : g_h1h[cur];
    const __nv_bfloat16* __restrict__ hl = (LAYER == 0) ? g_h0l[cur] : g_h1l[cur];
    const float* __restrict__ hinf       = (LAYER == 0) ? g_h0f[cur] : g_h1f[cur];
    float* __restrict__ houtf            = (LAYER == 0) ? g_h0f[nxt] : g_h1f[nxt];
    __nv_bfloat16* __restrict__ houth    = (LAYER == 0) ? g_h0h[nxt] : g_h1h[nxt];
    __nv_bfloat16* __restrict__ houtl    = (LAYER == 0) ? g_h0l[nxt] : g_h1l[nxt];
    const __nv_bfloat16* __restrict__ Wxh  = (LAYER == 0) ? g_w0xh : g_w1xh;
    const __nv_bfloat16* __restrict__ Wxl  = (LAYER == 0) ? g_w0xl : g_w1xl;
    const __nv_bfloat16* __restrict__ Whhh = (LAYER == 0) ? g_w0hh : g_w1hh;
    const __nv_bfloat16* __restrict__ Whhl = (LAYER == 0) ? g_w0hl : g_w1hl;

    const int tid  = threadIdx.x;
    const int w    = tid >> 5;
    const int l    = tid & 31;
    const int rg   = w & 3;           // row group: rows rg*16 .. rg*16+15
    const int ch   = w >> 2;          // col half: cols ch*16 .. ch*16+15
    const int rowBase = (blockIdx.x & 15) * TM;
    const int colBase = (blockIdx.x >> 4) * TN;
    const uint32_t smb = smem_u32(sm);

    // accumulators: [plane r,z,inn,hn][nf(2)][reg(4)] = 32 regs
    float cA[4][2][4];
    {
        const int c4 = l & 3;
        #pragma unroll
        for (int nf = 0; nf < 2; nf++) {
            const int j0 = colBase + ch * 16 + nf * 8 + 2 * c4;
            const float br0 = __ldg(bih + j0)     + __ldg(bhh + j0);
            const float br1 = __ldg(bih + j0 + 1) + __ldg(bhh + j0 + 1);
            const float bz0 = __ldg(bih + HID + j0)     + __ldg(bhh + HID + j0);
            const float bz1 = __ldg(bih + HID + j0 + 1) + __ldg(bhh + HID + j0 + 1);
            const float bi0 = __ldg(bih + 2 * HID + j0);
            const float bi1 = __ldg(bih + 2 * HID + j0 + 1);
            const float bn0 = __ldg(bhh + 2 * HID + j0);
            const float bn1 = __ldg(bhh + 2 * HID + j0 + 1);
            cA[0][nf][0] = br0; cA[0][nf][1] = br1; cA[0][nf][2] = br0; cA[0][nf][3] = br1;
            cA[1][nf][0] = bz0; cA[1][nf][1] = bz1; cA[1][nf][2] = bz0; cA[1][nf][3] = bz1;
            cA[2][nf][0] = bi0; cA[2][nf][1] = bi1; cA[2][nf][2] = bi0; cA[2][nf][3] = bi1;
            cA[3][nf][0] = bn0; cA[3][nf][1] = bn1; cA[3][nf][2] = bn0; cA[3][nf][3] = bn1;
        }
    }

    // ---- hoisted per-thread loader offsets (all pow2 shifts/masks) ----
    const int aRow   = rowBase + (tid >> 2);        // global A row
    const int akcOff = (tid & 3) << 3;              // k elem offset in tile
    const uint32_t aDst = (uint32_t)(((tid >> 2) * AST + ((tid & 3) << 3)) << 1);
    const int wPart  = tid >> 7;                    // 0 = hi, 1 = lo
    const int widx   = tid & 127;
    const int wRowG  = colBase + (widx >> 2);       // global W row (within plane 0)
    const int wkcOff = (widx & 3) << 3;
    const uint32_t wDst = (uint32_t)((((widx >> 2) * AST + ((widx & 3) << 3)) << 1));

    // ---- hoisted ldmatrix byte offsets ----
    const uint32_t aOffB =
        (uint32_t)(((rg * 16 + (l & 7) + (((l >> 3) & 1) << 3)) * AST + ((l >> 4) << 3)) << 1);
    const uint32_t wOffB =
        (uint32_t)(((ch * 16 + (l & 7) + (((l >> 4) & 1) << 3)) * AST + (((l >> 3) & 1) << 3)) << 1);

    auto stageT = [&](int t) {
        const int buf = t & 3;
        const bool xph = (t < NXT);
        const int K    = xph ? KPH0 : HID;
        const int koff = (xph ? t : t - NXT) * KT;
        const __nv_bfloat16* Ah = xph ? xh : hh;
        const __nv_bfloat16* Al = xph ? xl : hl;
        const uint32_t stg = smb + buf * G_STAGE;
        // A: thread covers (row, kc) for both hi and lo
        {
            const size_t g = (size_t)aRow * K + (koff + akcOff);
            cpa16(stg + aDst, Ah + g);
            cpa16(stg + G_APART + aDst, Al + g);
        }
        // W: thread covers one (row, kc) chunk of its part, looped over 3 planes
        const __nv_bfloat16* Wsrc = xph ? (wPart ? Wxl : Wxh) : (wPart ? Whhl : Whhh);
        const uint32_t wDstBase = stg + 2 * G_APART + wPart * G_WPART + wDst;
        #pragma unroll
        for (int p = 0; p < 3; p++) {
            const size_t g = (size_t)(p * HID + wRowG) * K + (koff + wkcOff);
            cpa16(wDstBase + p * (32 * AST * 2), Wsrc + g);
        }
    };

    auto computeT = [&](int t) {
        const int buf = t & 3;
        const bool xph = (t < NXT);
        const uint32_t stg = smb + buf * G_STAGE;
        const uint32_t aH = stg + aOffB;
        const uint32_t aL = stg + G_APART + aOffB;
        const uint32_t wH = stg + 2 * G_APART + wOffB;
        const uint32_t wL = stg + 2 * G_APART + G_WPART + wOffB;
        #pragma unroll
        for (int kc = 0; kc < 2; kc++) {
            uint32_t ah[4], al[4];
            ldsm4(ah, aH + kc * 32);
            ldsm4(al, aL + kc * 32);
            #pragma unroll
            for (int p = 0; p < 3; p++) {
                uint32_t bh[4], bl[4];
                ldsm4(bh, wH + p * (32 * AST * 2) + kc * 32);
                ldsm4(bl, wL + p * (32 * AST * 2) + kc * 32);
                float (*C)[4] = (p == 2) ? (xph ? cA[2] : cA[3]) : cA[p];
                #pragma unroll
                for (int nf = 0; nf < 2; nf++) {
                    mma_bf16(C[nf], ah, bh[2 * nf], bh[2 * nf + 1]);
                    mma_bf16(C[nf], al, bh[2 * nf], bh[2 * nf + 1]);
                    mma_bf16(C[nf], ah, bl[2 * nf], bl[2 * nf + 1]);
                }
            }
        }
    };

    stageT(0); cpa_commit();
    stageT(1); cpa_commit();
    stageT(2); cpa_commit();
    for (int t = 0; t < NT; t++) {
        cpa_wait<2>();
        __syncthreads();
        computeT(t);
        if (t + 3 < NT) stageT(t + 3);
        cpa_commit();
    }

    // GRU epilogue (hinf via __ldcg: L2-coherent cross-CTA reads)
    const int g  = l >> 2;
    const int c4 = l & 3;
    const int R0 = rowBase + rg * 16 + g;
    const int R1 = R0 + 8;
    #pragma unroll
    for (int nf = 0; nf < 2; nf++) {
        const int j0 = colBase + ch * 16 + nf * 8 + 2 * c4;
        const float2 h0v = __ldcg((const float2*)(hinf + (size_t)R0 * HID + j0));
        const float2 h1v = __ldcg((const float2*)(hinf + (size_t)R1 * HID + j0));
        float o[4];
        const float hvv[4] = { h0v.x, h0v.y, h1v.x, h1v.y };
        #pragma unroll
        for (int i = 0; i < 4; i++) {
            const float r_ = sigf(cA[0][nf][i]);
            const float z_ = sigf(cA[1][nf][i]);
            const float n_ = tanhf_fast(cA[2][nf][i] + r_ * cA[3][nf][i]);
            o[i] = (1.0f - z_) * n_ + z_ * hvv[i];
        }
        *(float2*)&houtf[(size_t)R0 * HID + j0] = make_float2(o[0], o[1]);
        *(float2*)&houtf[(size_t)R1 * HID + j0] = make_float2(o[2], o[3]);
        __nv_bfloat16 h0a, l0a, h0b, l0b, h1a, l1a, h1b, l1b;
        split_bf16(o[0], h0a, l0a); split_bf16(o[1], h0b, l0b);
        split_bf16(o[2], h1a, l1a); split_bf16(o[3], h1b, l1b);
        *(__nv_bfloat162*)&houth[(size_t)R0 * HID + j0] = __halves2bfloat162(h0a, h0b);
        *(__nv_bfloat162*)&houtl[(size_t)R0 * HID + j0] = __halves2bfloat162(l0a, l0b);
        *(__nv_bfloat162*)&houth[(size_t)R1 * HID + j0] = __halves2bfloat162(h1a, h1b);
        *(__nv_bfloat162*)&houtl[(size_t)R1 * HID + j0] = __halves2bfloat162(l1a, l1b);
    }
}

// ---------------------------------------------------------------------------
// Output head: warp-per-row on CTAs 0..127 (1024 rows), Wout/bias reads L2-hot.
// ---------------------------------------------------------------------------
__device__ __forceinline__ void head_step(int cur,
                                          const float* __restrict__ Wout,
                                          const float* __restrict__ bout,
                                          float* __restrict__ outputs, int step)
{
    const int nxt  = cur ^ 1;
    const int w    = threadIdx.x >> 5;
    const int lane = threadIdx.x & 31;
    const int row  = blockIdx.x * 8 + w;
    const float* __restrict__ h1 = g_h1f[nxt];

    float xv[16];
    {
        const float4* hr = (const float4*)(h1 + (size_t)row * HID);
        #pragma unroll
        for (int q = 0; q < 4; q++) {
            float4 v = __ldcg(&hr[lane * 4 + q]);
            xv[q * 4 + 0] = fmaxf(v.x, 0.f);
            xv[q * 4 + 1] = fmaxf(v.y, 0.f);
            xv[q * 4 + 2] = fmaxf(v.z, 0.f);
            xv[q * 4 + 3] = fmaxf(v.w, 0.f);
        }
    }

    float s[TSZ];
    #pragma unroll
    for (int j = 0; j < TSZ; j++) {
        const float4* wr = (const float4*)(Wout + (size_t)j * HID + lane * 16);
        float a = 0.f;
        #pragma unroll
        for (int q = 0; q < 4; q++) {
            const float4 wv = __ldg(&wr[q]);
            a = fmaf(xv[q * 4 + 0], wv.x, a);
            a = fmaf(xv[q * 4 + 1], wv.y, a);
            a = fmaf(xv[q * 4 + 2], wv.z, a);
            a = fmaf(xv[q * 4 + 3], wv.w, a);
        }
        s[j] = a;
    }

    #pragma unroll
    for (int off = 16; off >= 1; off >>= 1) {
        #pragma unroll
        for (int j = 0; j < TSZ; j++)
            s[j] += __shfl_xor_sync(0xFFFFFFFFu, s[j], off);
    }

    if (lane < TSZ) {
        const float v = sigf(s[lane] + __ldg(bout + lane));
        outputs[(size_t)row * (PLEN * TSZ) + (size_t)step * TSZ + lane] = v;
        __nv_bfloat16 vh, vl;
        split_bf16(v, vh, vl);
        g_valh[nxt][row * XP0 + lane] = vh;
        g_vall[nxt][row * XP0 + lane] = vl;
    }
}

// ---------------------------------------------------------------------------
// Persistent whole-rollout kernel: 256 CTAs (2/SM), 3 grid barriers per step.
// ---------------------------------------------------------------------------
__global__ __launch_bounds__(256, 2)
void decoder_persistent(const float* __restrict__ bih0, const float* __restrict__ bhh0,
                        const float* __restrict__ bih1, const float* __restrict__ bhh1,
                        const float* __restrict__ Wout, const float* __restrict__ bout,
                        float* __restrict__ out)
{
    extern __shared__ __align__(16) char sm[];
    unsigned target = 0;

    for (int s = 0; s < PLEN; s++) {
        const int cur = s & 1;
        gru_layer_step<0>(sm, cur, bih0, bhh0);
        target += NCTA; grid_barrier(target);
        gru_layer_step<1>(sm, cur, bih1, bhh1);
        target += NCTA; grid_barrier(target);
        if (blockIdx.x < BATCH / 8) head_step(cur, Wout, bout, out, s);
        target += NCTA; grid_barrier(target);
    }

    // final hidden copy: after 256 steps (even), state sits in buffer 0
    constexpr int CH = BATCH * HID / NCTA;   // 2048
    const int base = blockIdx.x * CH;
    float* dst = out + (size_t)BATCH * PLEN * TSZ;
    for (int i = threadIdx.x; i < CH; i += blockDim.x) {
        dst[base + i]               = __ldcg(&g_h0f[0][base + i]);
        dst[BATCH * HID + base + i] = __ldcg(&g_h1f[0][base + i]);
    }
}

// ---------------------------------------------------------------------------
// init: reset barrier, copy/split initial hidden, zero val, split weights
// ---------------------------------------------------------------------------
__global__ void init_kernel(const float* __restrict__ hidden,
                            const float* __restrict__ Wih0,
                            const float* __restrict__ Whh0,
                            const float* __restrict__ Wih1,
                            const float* __restrict__ Whh1)
{
    const int i = blockIdx.x * blockDim.x + threadIdx.x;
    const __nv_bfloat16 z16 = __float2bfloat16(0.0f);

    if (i == 0) g_barcnt = 0;

    if (i < BATCH * HID) {
        const float a = hidden[i];
        const float b = hidden[BATCH * HID + i];
        g_h0f[0][i] = a;
        g_h1f[0][i] = b;
        split_bf16(a, g_h0h[0][i], g_h0l[0][i]);
        split_bf16(b, g_h1h[0][i], g_h1l[0][i]);
    }
    if (i < 2 * BATCH * XP0) {
        (&g_valh[0][0])[i] = z16;
        (&g_vall[0][0])[i] = z16;
    }
    if (i < 3 * HID * XP0) {
        const int r = i / XP0;
        const int k = i % XP0;
        const float ww = (k < TSZ) ? Wih0[r * TSZ + k] : 0.0f;
        split_bf16(ww, g_w0xh[i], g_w0xl[i]);
    }
    if (i < 3 * HID * HID) {
        split_bf16(Whh0[i], g_w0hh[i], g_w0hl[i]);
        split_bf16(Wih1[i], g_w1xh[i], g_w1xl[i]);
        split_bf16(Whh1[i], g_w1hh[i], g_w1hl[i]);
    }
}

// ---------------------------------------------------------------------------
// host
// ---------------------------------------------------------------------------
extern "C" void kernel_launch(void* const* d_in, const int* in_sizes, int n_in,
                              void* d_out, int out_size)
{
    const float* hidden = (const float*)d_in[0];
    const float* Wih0   = (const float*)d_in[1];
    const float* Whh0   = (const float*)d_in[2];
    const float* bih0   = (const float*)d_in[3];
    const float* bhh0   = (const float*)d_in[4];
    const float* Wih1   = (const float*)d_in[5];
    const float* Whh1   = (const float*)d_in[6];
    const float* bih1   = (const float*)d_in[7];
    const float* bhh1   = (const float*)d_in[8];
    const float* Wout   = (const float*)d_in[9];
    const float* bout   = (const float*)d_in[10];
    float* out = (float*)d_out;

    cudaFuncSetAttribute(decoder_persistent,
                         cudaFuncAttributeMaxDynamicSharedMemorySize, G_SMEM);

    init_kernel<<<(3 * HID * HID + 255) / 256, 256>>>(hidden, Wih0, Whh0, Wih1, Whh1);
    decoder_persistent<<<NCTA, 256, G_SMEM>>>(bih0, bhh0, bih1, bhh1, Wout, bout, out);
}